// round 9
// baseline (speedup 1.0000x reference)
#include <cuda_runtime.h>
#include <cuda_bf16.h>
#include <cuda_fp16.h>
#include <math.h>
#include <stdint.h>

#define BB 4
#define SS 2048
#define DD 1024
#define HH 16
#define AA 64
#define NN (HH*AA)   // 1024
#define BSD (BB*SS*DD)

typedef __nv_bfloat16 bf16;
typedef __nv_bfloat162 bf162;

// ---- scratch ----
__device__ bf16 g_qhi[BB*HH*SS*AA];
__device__ bf16 g_qlo[BB*HH*SS*AA];
__device__ bf16 g_khi[BB*HH*SS*AA];
__device__ bf16 g_klo[BB*HH*SS*AA];
__device__ __half g_vh2[BB*HH*SS*AA];        // V single fp16
__device__ bf16 g_xhi[3*BSD];
__device__ bf16 g_xlo[3*BSD];
__device__ bf16 g_whi[3*NN*DD];
__device__ bf16 g_wlo[3*NN*DD];

// ======================= helpers =======================
__device__ __forceinline__ uint32_t smem_u32(const void* p) {
    uint32_t a;
    asm("{ .reg .u64 t; cvta.to.shared.u64 t, %1; cvt.u32.u64 %0, t; }" : "=r"(a) : "l"(p));
    return a;
}
__device__ __forceinline__ void mma16816(float* c, const uint32_t* a, const uint32_t* b) {
    asm volatile(
        "mma.sync.aligned.m16n8k16.row.col.f32.bf16.bf16.f32 "
        "{%0,%1,%2,%3}, {%4,%5,%6,%7}, {%8,%9}, {%0,%1,%2,%3};"
        : "+f"(c[0]), "+f"(c[1]), "+f"(c[2]), "+f"(c[3])
        : "r"(a[0]), "r"(a[1]), "r"(a[2]), "r"(a[3]), "r"(b[0]), "r"(b[1]));
}
__device__ __forceinline__ void mma16816h(float* c, const uint32_t* a, const uint32_t* b) {
    asm volatile(
        "mma.sync.aligned.m16n8k16.row.col.f32.f16.f16.f32 "
        "{%0,%1,%2,%3}, {%4,%5,%6,%7}, {%8,%9}, {%0,%1,%2,%3};"
        : "+f"(c[0]), "+f"(c[1]), "+f"(c[2]), "+f"(c[3])
        : "r"(a[0]), "r"(a[1]), "r"(a[2]), "r"(a[3]), "r"(b[0]), "r"(b[1]));
}
__device__ __forceinline__ void ldsm4(uint32_t* r, uint32_t addr) {
    asm volatile("ldmatrix.sync.aligned.m8n8.x4.shared.b16 {%0,%1,%2,%3}, [%4];"
        : "=r"(r[0]), "=r"(r[1]), "=r"(r[2]), "=r"(r[3]) : "r"(addr));
}
__device__ __forceinline__ void ldsm4t(uint32_t* r, uint32_t addr) {
    asm volatile("ldmatrix.sync.aligned.m8n8.x4.trans.shared.b16 {%0,%1,%2,%3}, [%4];"
        : "=r"(r[0]), "=r"(r[1]), "=r"(r[2]), "=r"(r[3]) : "r"(addr));
}
#define CPA16(dst_u32, src_ptr) \
    asm volatile("cp.async.cg.shared.global [%0], [%1], 16;" :: "r"(dst_u32), "l"(src_ptr))
#define CPA_COMMIT() asm volatile("cp.async.commit_group;" ::: "memory")
#define CPA_WAIT(n)  asm volatile("cp.async.wait_group %0;" :: "n"(n) : "memory")

__device__ __forceinline__ float ex2f(float x) {
    float r;
    asm("ex2.approx.f32 %0, %1;" : "=f"(r) : "f"(x));
    return r;
}
__device__ __forceinline__ uint32_t ex2h2(uint32_t a) {
    uint32_t r;
    asm("ex2.approx.f16x2 %0, %1;" : "=r"(r) : "r"(a));
    return r;
}
__device__ __forceinline__ uint32_t packh2(float a, float b) {
    __half2 h = __floats2half2_rn(a, b);      // x = a (low), y = b (high)
    return *reinterpret_cast<uint32_t*>(&h);
}
__device__ __forceinline__ uint32_t packbf2(float a, float b) {
    bf162 h = __floats2bfloat162_rn(a, b);
    return *reinterpret_cast<uint32_t*>(&h);
}
__device__ __forceinline__ void split2(float p0, float p1, uint32_t& hi, uint32_t& lo) {
    bf162 h = __floats2bfloat162_rn(p0, p1);
    bf162 l = __floats2bfloat162_rn(p0 - __bfloat162float(h.x), p1 - __bfloat162float(h.y));
    hi = *reinterpret_cast<uint32_t*>(&h);
    lo = *reinterpret_cast<uint32_t*>(&l);
}
#define L2E 1.4426950408889634f
#define ONESH2 0x3C003C00u                    // fp16 (1.0, 1.0)

// ======================= conversion kernels (fused over q,k,v) =======================
__global__ __launch_bounds__(256) void cvt_x3(const float* __restrict__ q,
                                              const float* __restrict__ k,
                                              const float* __restrict__ v) {
    const int which = blockIdx.y;
    const float* X = (which == 0) ? q : (which == 1) ? k : v;
    bf16* xh = g_xhi + (size_t)which * BSD;
    bf16* xl = g_xlo + (size_t)which * BSD;
    int i = blockIdx.x * 256 + threadIdx.x;    // 0..BSD/8-1
    float4 a = ((const float4*)X)[2*i];
    float4 b = ((const float4*)X)[2*i+1];
    float f[8] = {a.x, a.y, a.z, a.w, b.x, b.y, b.z, b.w};
    uint32_t hw[4], lw[4];
    #pragma unroll
    for (int j = 0; j < 4; j++) {
        bf16 h0 = __float2bfloat16(f[2*j]);
        bf16 h1 = __float2bfloat16(f[2*j+1]);
        float l0 = f[2*j]   - __bfloat162float(h0);
        float l1 = f[2*j+1] - __bfloat162float(h1);
        bf162 hh = __halves2bfloat162(h0, h1);
        hw[j] = *reinterpret_cast<uint32_t*>(&hh);
        lw[j] = packbf2(l0, l1);
    }
    ((uint4*)xh)[i] = make_uint4(hw[0], hw[1], hw[2], hw[3]);
    ((uint4*)xl)[i] = make_uint4(lw[0], lw[1], lw[2], lw[3]);
}
__global__ __launch_bounds__(256) void cvt_w3(const float* __restrict__ Wq,
                                              const float* __restrict__ Wk,
                                              const float* __restrict__ Wv) {
    const int which = blockIdx.y;
    const float* W = (which == 0) ? Wq : (which == 1) ? Wk : Wv;
    bf16* wh = g_whi + (size_t)which * (NN * DD);
    bf16* wl = g_wlo + (size_t)which * (NN * DD);
    int idx = blockIdx.x * 256 + threadIdx.x;
    float4 wv = ((const float4*)W)[idx];
    int a4 = idx & 15;
    int d  = (idx >> 4) & 1023;
    int h  = idx >> 14;
    int nb = h * AA + a4 * 4;
    float vals[4] = {wv.x, wv.y, wv.z, wv.w};
    #pragma unroll
    for (int j = 0; j < 4; j++) {
        bf16 hi = __float2bfloat16(vals[j]);
        bf16 lo = __float2bfloat16(vals[j] - __bfloat162float(hi));
        size_t o = (size_t)(nb + j) * DD + d;
        wh[o] = hi;
        wl[o] = lo;
    }
}

// ======================= projection GEMM =======================
// block tile 128x128, 256 threads, warps 4(m) x 2(n), warp tile 32x64.
// 3-stage cp.async ring, ONE barrier per K-chunk.
// hi tiles padded (XPH=40), lo tiles unpadded (XPL=32; 2-way ldsm conflict, acceptable).
#define KC 32
#define XPH 40
#define XPL 32
#define OFF_XL (128*XPH*2)                     // 10240 B: Xlo after Xhi
#define OFF_WH (OFF_XL + 128*XPL*2)            // 18432
#define OFF_WL (OFF_WH + 128*XPH*2)            // 28672
#define PSTG_B (OFF_WL + 128*XPL*2)            // 36864 bytes per stage
#define PROJ_SMEM (3*PSTG_B)                   // 110592

__global__ __launch_bounds__(256, 2) void proj_mma(const float* __restrict__ bq,
                                                   const float* __restrict__ bk,
                                                   const float* __restrict__ bv) {
    const int which = blockIdx.z;
    const float* bias = (which == 0) ? bq : (which == 1) ? bk : bv;
    const bf16* Xh = g_xhi + (size_t)which * BSD;
    const bf16* Xl = g_xlo + (size_t)which * BSD;
    const bf16* Wh = g_whi + (size_t)which * (NN * DD);
    const bf16* Wl = g_wlo + (size_t)which * (NN * DD);
    extern __shared__ bf16 sm[];
    const int t = threadIdx.x, lane = t & 31, wid = t >> 5;
    const int wm = wid & 3, wn = wid >> 2;
    const int r0 = blockIdx.x * 128, n0 = blockIdx.y * 128;
    const uint32_t sbase = smem_u32(sm);

    float c[2][8][4];
    #pragma unroll
    for (int mt = 0; mt < 2; mt++)
        #pragma unroll
        for (int nt = 0; nt < 8; nt++)
            #pragma unroll
            for (int i = 0; i < 4; i++) c[mt][nt][i] = 0.0f;

    // 8 cp.async of 16B per thread per chunk (256 threads, 4 tiles of 128x32)
#define PROJ_ISSUE(kc_) do {                                                       \
    int k0_ = (kc_) * KC;                                                          \
    uint32_t stg_ = sbase + ((kc_) % 3) * PSTG_B;                                  \
    _Pragma("unroll")                                                              \
    for (int i = 0; i < 8; i++) {                                                  \
        int rem = ((i & 1) << 8) + t; int row = rem >> 2, cq = rem & 3;            \
        const bf16* src;  uint32_t dst;                                            \
        if      ((i >> 1) == 0) { src = Xh + (size_t)(r0 + row) * DD + k0_ + cq * 8; \
                                  dst = stg_ + (row * XPH + cq * 8) * 2; }         \
        else if ((i >> 1) == 1) { src = Xl + (size_t)(r0 + row) * DD + k0_ + cq * 8; \
                                  dst = stg_ + OFF_XL + (row * XPL + cq * 8) * 2; } \
        else if ((i >> 1) == 2) { src = Wh + (size_t)(n0 + row) * DD + k0_ + cq * 8; \
                                  dst = stg_ + OFF_WH + (row * XPH + cq * 8) * 2; } \
        else                    { src = Wl + (size_t)(n0 + row) * DD + k0_ + cq * 8; \
                                  dst = stg_ + OFF_WL + (row * XPL + cq * 8) * 2; } \
        CPA16(dst, src);                                                           \
    } } while (0)

    PROJ_ISSUE(0);
    CPA_COMMIT();
    #pragma unroll 1
    for (int kc = 0; kc < DD / KC; kc++) {
        if (kc + 1 < DD / KC) {
            PROJ_ISSUE(kc + 1);
            CPA_COMMIT();
            CPA_WAIT(1);
        } else {
            CPA_WAIT(0);
        }
        __syncthreads();   // single barrier per chunk (3-stage ring makes bottom barrier unnecessary)

        const uint32_t stage = sbase + (kc % 3) * PSTG_B;
        #pragma unroll
        for (int ka = 0; ka < 2; ka++) {
            const int kk = ka * 16;
            uint32_t xh[2][4], xl[2][4];
            #pragma unroll
            for (int mt = 0; mt < 2; mt++) {
                int arow = wm * 32 + mt * 16 + (lane & 15);
                int acol = kk + (lane >> 4) * 8;
                ldsm4(xh[mt], stage + (arow * XPH + acol) * 2);
                ldsm4(xl[mt], stage + OFF_XL + (arow * XPL + acol) * 2);
            }
            #pragma unroll
            for (int jp = 0; jp < 4; jp++) {
                uint32_t wh[4], wl[4];
                int brow = wn * 64 + jp * 16 + (lane & 7) + ((lane & 16) ? 8 : 0);
                int bcol = kk + ((lane >> 3) & 1) * 8;
                ldsm4(wh, stage + OFF_WH + (brow * XPH + bcol) * 2);
                ldsm4(wl, stage + OFF_WL + (brow * XPL + bcol) * 2);
                #pragma unroll
                for (int mt = 0; mt < 2; mt++) {
                    mma16816(c[mt][2*jp],   xh[mt], &wh[0]);
                    mma16816(c[mt][2*jp],   xh[mt], &wl[0]);
                    mma16816(c[mt][2*jp],   xl[mt], &wh[0]);
                    mma16816(c[mt][2*jp+1], xh[mt], &wh[2]);
                    mma16816(c[mt][2*jp+1], xh[mt], &wl[2]);
                    mma16816(c[mt][2*jp+1], xl[mt], &wh[2]);
                }
            }
        }
    }

    // epilogue
    const int g = lane >> 2, l = lane & 3;
    #pragma unroll
    for (int mt = 0; mt < 2; mt++) {
        int row = r0 + wm * 32 + mt * 16 + g;
        int b = row >> 11, s = row & (SS - 1);
        #pragma unroll
        for (int nt = 0; nt < 8; nt++) {
            int n = n0 + wn * 64 + nt * 8 + l * 2;
            int h = n >> 6, a = n & 63;
            size_t off = ((size_t)(b * HH + h) * SS + s) * AA + a;
            float bv0 = bias[n], bv1 = bias[n + 1];
            float p0 = c[mt][nt][0] + bv0, p1 = c[mt][nt][1] + bv1;
            float p2 = c[mt][nt][2] + bv0, p3 = c[mt][nt][3] + bv1;
            if (which == 2) {
                *(uint32_t*)(g_vh2 + off)          = packh2(p0, p1);
                *(uint32_t*)(g_vh2 + off + 8 * AA) = packh2(p2, p3);
            } else {
                bf16 *outhi = (which == 0) ? g_qhi : g_khi;
                bf16 *outlo = (which == 0) ? g_qlo : g_klo;
                uint32_t hi, lo;
                split2(p0, p1, hi, lo);
                *(uint32_t*)(outhi + off) = hi;
                *(uint32_t*)(outlo + off) = lo;
                split2(p2, p3, hi, lo);
                *(uint32_t*)(outhi + off + 8 * AA) = hi;
                *(uint32_t*)(outlo + off + 8 * AA) = lo;
            }
        }
    }
}

// ======================= flash attention (unchanged from R8) =======================
#define QP 72
#define ASTG_H (3*64*QP)                       // Khi, Klo, V
#define ASTG_B (ASTG_H*2)                      // 27648 bytes
#define OFF_QL (128*QP*2)
#define OFF_ST (256*QP*2)                      // 36864
#define ATTN_SMEM (OFF_ST + 2*ASTG_B)          // 92160 bytes

__global__ __launch_bounds__(256, 2) void attn_mma(float* __restrict__ out) {
    extern __shared__ bf16 smh[];
    bf16* Qh = smh;
    bf16* Ql = Qh + 128 * QP;

    const int bh = blockIdx.y, q0 = blockIdx.x * 128;
    const int t = threadIdx.x, lane = t & 31, wid = t >> 5;
    const int m0w = wid * 16;
    const size_t bhoff = (size_t)bh * SS * AA;
    const uint32_t sb = smem_u32(smh);

#define ATTN_ISSUE(kt_) do {                                                      \
    const size_t toff_ = bhoff + (size_t)(kt_) * 64 * AA;                         \
    uint32_t stg_ = sb + OFF_ST + ((kt_) & 1) * ASTG_B;                           \
    _Pragma("unroll")                                                             \
    for (int i = 0; i < 2; i++) {                                                 \
        int idx = t + i * 256; int row = idx >> 3, cq = idx & 7;                  \
        uint32_t so = stg_ + (row * QP + cq * 8) * 2;                             \
        size_t go = toff_ + row * AA + cq * 8;                                    \
        CPA16(so,              g_khi + go);                                       \
        CPA16(so + 64*QP*2,    g_klo + go);                                       \
        CPA16(so + 128*QP*2,   g_vh2 + go);                                       \
    } } while (0)

    {
        const bf16* Qghi = g_qhi + bhoff + (size_t)q0 * AA;
        const bf16* Qglo = g_qlo + bhoff + (size_t)q0 * AA;
        #pragma unroll
        for (int i = 0; i < 4; i++) {
            int idx = t + i * 256;
            int row = idx >> 3, cq = idx & 7;
            *(uint4*)(Qh + row * QP + cq * 8) = *(const uint4*)(Qghi + row * AA + cq * 8);
            *(uint4*)(Ql + row * QP + cq * 8) = *(const uint4*)(Qglo + row * AA + cq * 8);
        }
    }

    ATTN_ISSUE(0);
    CPA_COMMIT();

    float o[8][4];
    float ls[4] = {0.0f, 0.0f, 0.0f, 0.0f};
    #pragma unroll
    for (int j = 0; j < 8; j++)
        #pragma unroll
        for (int i = 0; i < 4; i++) o[j][i] = 0.0f;
    float mi0 = -INFINITY, mi1 = -INFINITY;
    const uint32_t onesb[2] = {ONESH2, ONESH2};

    #pragma unroll 1
    for (int kt = 0; kt < SS / 64; kt++) {
        if (kt + 1 < SS / 64) {
            ATTN_ISSUE(kt + 1);
            CPA_COMMIT();
            CPA_WAIT(1);
        } else {
            CPA_WAIT(0);
        }
        __syncthreads();
        const uint32_t stg = sb + OFF_ST + (kt & 1) * ASTG_B;

        float s[8][4];
        #pragma unroll
        for (int j = 0; j < 8; j++)
            #pragma unroll
            for (int i = 0; i < 4; i++) s[j][i] = 0.0f;

        #pragma unroll
        for (int ka = 0; ka < 4; ka++) {
            const int a0 = ka * 16;
            uint32_t qh[4], ql[4];
            uint32_t qaddr = sb + ((m0w + (lane & 15)) * QP + a0 + (lane >> 4) * 8) * 2;
            ldsm4(qh, qaddr);
            ldsm4(ql, qaddr + OFF_QL);
            #pragma unroll
            for (int jp = 0; jp < 4; jp++) {
                uint32_t kh4[4], kl4[4];
                int krow = jp * 16 + (lane & 7) + ((lane & 16) ? 8 : 0);
                uint32_t kaddr = stg + (krow * QP + a0 + ((lane >> 3) & 1) * 8) * 2;
                ldsm4(kh4, kaddr);
                ldsm4(kl4, kaddr + 64 * QP * 2);
                mma16816(s[2*jp],   qh, &kh4[0]);
                mma16816(s[2*jp],   qh, &kl4[0]);
                mma16816(s[2*jp],   ql, &kh4[0]);
                mma16816(s[2*jp+1], qh, &kh4[2]);
                mma16816(s[2*jp+1], qh, &kl4[2]);
                mma16816(s[2*jp+1], ql, &kh4[2]);
            }
        }

        float tm0 = -INFINITY, tm1 = -INFINITY;
        #pragma unroll
        for (int j = 0; j < 8; j++) {
            tm0 = fmaxf(tm0, fmaxf(s[j][0], s[j][1]));
            tm1 = fmaxf(tm1, fmaxf(s[j][2], s[j][3]));
        }
        tm0 = fmaxf(tm0, __shfl_xor_sync(0xffffffffu, tm0, 1));
        tm0 = fmaxf(tm0, __shfl_xor_sync(0xffffffffu, tm0, 2));
        tm1 = fmaxf(tm1, __shfl_xor_sync(0xffffffffu, tm1, 1));
        tm1 = fmaxf(tm1, __shfl_xor_sync(0xffffffffu, tm1, 2));
        float mn0 = fmaxf(mi0, tm0), mn1 = fmaxf(mi1, tm1);
        if (tm0 > mi0 || tm1 > mi1) {
            float corr0 = ex2f((mi0 - mn0) * L2E);
            float corr1 = ex2f((mi1 - mn1) * L2E);
            #pragma unroll
            for (int j = 0; j < 8; j++) {
                o[j][0] *= corr0; o[j][1] *= corr0;
                o[j][2] *= corr1; o[j][3] *= corr1;
            }
            ls[0] *= corr0; ls[1] *= corr0; ls[2] *= corr1; ls[3] *= corr1;
            mi0 = mn0; mi1 = mn1;
        }
        const float b0 = -mi0 * L2E, b1 = -mi1 * L2E;
        uint32_t ps[8][2];
        #pragma unroll
        for (int j = 0; j < 8; j++) {
            ps[j][0] = ex2h2(packh2(fmaf(s[j][0], L2E, b0), fmaf(s[j][1], L2E, b0)));
            ps[j][1] = ex2h2(packh2(fmaf(s[j][2], L2E, b1), fmaf(s[j][3], L2E, b1)));
        }

        #pragma unroll
        for (int kc = 0; kc < 4; kc++) {
            uint32_t pa[4];
            pa[0] = ps[2*kc][0];
            pa[1] = ps[2*kc][1];
            pa[2] = ps[2*kc+1][0];
            pa[3] = ps[2*kc+1][1];
            mma16816h(ls, pa, onesb);
            #pragma unroll
            for (int jp = 0; jp < 4; jp++) {
                uint32_t vh4[4];
                int vrow = kc * 16 + (lane & 7) + ((lane >> 3) & 1) * 8;
                uint32_t vaddr = stg + 128 * QP * 2 +
                    (vrow * QP + jp * 16 + ((lane & 16) ? 8 : 0)) * 2;
                ldsm4t(vh4, vaddr);
                mma16816h(o[2*jp],   pa, &vh4[0]);
                mma16816h(o[2*jp+1], pa, &vh4[2]);
            }
        }
        __syncthreads();
    }

    const float inv0 = 1.0f / ls[0], inv1 = 1.0f / ls[2];
    const int g = lane >> 2, l = lane & 3;
    const int b = bh >> 4, h = bh & 15;
    const int row0 = q0 + m0w + g;
    float* outp = out + ((size_t)b * SS + row0) * NN + h * AA;
    #pragma unroll
    for (int j = 0; j < 8; j++) {
        float2 w0 = make_float2(o[j][0] * inv0, o[j][1] * inv0);
        float2 w1 = make_float2(o[j][2] * inv1, o[j][3] * inv1);
        *(float2*)(outp + j * 8 + l * 2) = w0;
        *(float2*)(outp + (size_t)8 * NN + j * 8 + l * 2) = w1;
    }
}

extern "C" void kernel_launch(void* const* d_in, const int* in_sizes, int n_in,
                              void* d_out, int out_size) {
    (void)in_sizes; (void)n_in; (void)out_size;
    const float* q  = (const float*)d_in[0];
    const float* k  = (const float*)d_in[1];
    const float* v  = (const float*)d_in[2];
    const float* Wq = (const float*)d_in[3];
    const float* bq = (const float*)d_in[4];
    const float* Wk = (const float*)d_in[5];
    const float* bk = (const float*)d_in[6];
    const float* Wv = (const float*)d_in[7];
    const float* bv = (const float*)d_in[8];
    float* out = (float*)d_out;

    cudaFuncSetAttribute(proj_mma, cudaFuncAttributeMaxDynamicSharedMemorySize, PROJ_SMEM);
    cudaFuncSetAttribute(attn_mma, cudaFuncAttributeMaxDynamicSharedMemorySize, ATTN_SMEM);

    cvt_x3<<<dim3(4096, 3), 256>>>(q, k, v);
    cvt_w3<<<dim3(1024, 3), 256>>>(Wq, Wk, Wv);
    proj_mma<<<dim3(64, 8, 3), 256, PROJ_SMEM>>>(bq, bk, bv);

    dim3 ag(SS / 128, BB * HH);
    attn_mma<<<ag, 256, ATTN_SMEM>>>(out);
}

// round 11
// speedup vs baseline: 1.0591x; 1.0591x over previous
#include <cuda_runtime.h>
#include <cuda_bf16.h>
#include <cuda_fp16.h>
#include <math.h>
#include <stdint.h>

#define BB 4
#define SS 2048
#define DD 1024
#define HH 16
#define AA 64
#define NN (HH*AA)   // 1024
#define BSD (BB*SS*DD)

typedef __nv_bfloat16 bf16;
typedef __nv_bfloat162 bf162;

// ---- scratch ----
__device__ bf16 g_qhi[BB*HH*SS*AA];
__device__ bf16 g_qlo[BB*HH*SS*AA];
__device__ bf16 g_khi[BB*HH*SS*AA];
__device__ bf16 g_klo[BB*HH*SS*AA];
__device__ __half g_vh2[BB*HH*SS*AA];        // V single fp16
__device__ bf16 g_xhi[3*BSD];
__device__ bf16 g_xlo[3*BSD];
__device__ bf16 g_whi[3*NN*DD];
__device__ bf16 g_wlo[3*NN*DD];

// ======================= helpers =======================
__device__ __forceinline__ uint32_t smem_u32(const void* p) {
    uint32_t a;
    asm("{ .reg .u64 t; cvta.to.shared.u64 t, %1; cvt.u32.u64 %0, t; }" : "=r"(a) : "l"(p));
    return a;
}
__device__ __forceinline__ void mma16816(float* c, const uint32_t* a, const uint32_t* b) {
    asm volatile(
        "mma.sync.aligned.m16n8k16.row.col.f32.bf16.bf16.f32 "
        "{%0,%1,%2,%3}, {%4,%5,%6,%7}, {%8,%9}, {%0,%1,%2,%3};"
        : "+f"(c[0]), "+f"(c[1]), "+f"(c[2]), "+f"(c[3])
        : "r"(a[0]), "r"(a[1]), "r"(a[2]), "r"(a[3]), "r"(b[0]), "r"(b[1]));
}
__device__ __forceinline__ void mma16816h(float* c, const uint32_t* a, const uint32_t* b) {
    asm volatile(
        "mma.sync.aligned.m16n8k16.row.col.f32.f16.f16.f32 "
        "{%0,%1,%2,%3}, {%4,%5,%6,%7}, {%8,%9}, {%0,%1,%2,%3};"
        : "+f"(c[0]), "+f"(c[1]), "+f"(c[2]), "+f"(c[3])
        : "r"(a[0]), "r"(a[1]), "r"(a[2]), "r"(a[3]), "r"(b[0]), "r"(b[1]));
}
__device__ __forceinline__ void ldsm4(uint32_t* r, uint32_t addr) {
    asm volatile("ldmatrix.sync.aligned.m8n8.x4.shared.b16 {%0,%1,%2,%3}, [%4];"
        : "=r"(r[0]), "=r"(r[1]), "=r"(r[2]), "=r"(r[3]) : "r"(addr));
}
__device__ __forceinline__ void ldsm4t(uint32_t* r, uint32_t addr) {
    asm volatile("ldmatrix.sync.aligned.m8n8.x4.trans.shared.b16 {%0,%1,%2,%3}, [%4];"
        : "=r"(r[0]), "=r"(r[1]), "=r"(r[2]), "=r"(r[3]) : "r"(addr));
}
#define CPA16(dst_u32, src_ptr) \
    asm volatile("cp.async.cg.shared.global [%0], [%1], 16;" :: "r"(dst_u32), "l"(src_ptr))
#define CPA_COMMIT() asm volatile("cp.async.commit_group;" ::: "memory")
#define CPA_WAIT(n)  asm volatile("cp.async.wait_group %0;" :: "n"(n) : "memory")

__device__ __forceinline__ float ex2f(float x) {
    float r;
    asm("ex2.approx.f32 %0, %1;" : "=f"(r) : "f"(x));
    return r;
}
__device__ __forceinline__ uint32_t ex2h2(uint32_t a) {
    uint32_t r;
    asm("ex2.approx.f16x2 %0, %1;" : "=r"(r) : "r"(a));
    return r;
}
__device__ __forceinline__ uint32_t packh2(float a, float b) {
    __half2 h = __floats2half2_rn(a, b);      // x = a (low), y = b (high)
    return *reinterpret_cast<uint32_t*>(&h);
}
__device__ __forceinline__ uint32_t packbf2(float a, float b) {
    bf162 h = __floats2bfloat162_rn(a, b);
    return *reinterpret_cast<uint32_t*>(&h);
}
__device__ __forceinline__ void split2(float p0, float p1, uint32_t& hi, uint32_t& lo) {
    bf162 h = __floats2bfloat162_rn(p0, p1);
    bf162 l = __floats2bfloat162_rn(p0 - __bfloat162float(h.x), p1 - __bfloat162float(h.y));
    hi = *reinterpret_cast<uint32_t*>(&h);
    lo = *reinterpret_cast<uint32_t*>(&l);
}
#define L2E 1.4426950408889634f
#define ONESH2 0x3C003C00u                    // fp16 (1.0, 1.0)
#define SW64(o) ((o) ^ (((o) >> 3) & 0x30))   // conflict-free swizzle for 64B rows

// ======================= conversion kernels (fused over q,k,v) =======================
__global__ __launch_bounds__(256) void cvt_x3(const float* __restrict__ q,
                                              const float* __restrict__ k,
                                              const float* __restrict__ v) {
    const int which = blockIdx.y;
    const float* X = (which == 0) ? q : (which == 1) ? k : v;
    bf16* xh = g_xhi + (size_t)which * BSD;
    bf16* xl = g_xlo + (size_t)which * BSD;
    int i = blockIdx.x * 256 + threadIdx.x;    // 0..BSD/8-1
    float4 a = ((const float4*)X)[2*i];
    float4 b = ((const float4*)X)[2*i+1];
    float f[8] = {a.x, a.y, a.z, a.w, b.x, b.y, b.z, b.w};
    uint32_t hw[4], lw[4];
    #pragma unroll
    for (int j = 0; j < 4; j++) {
        bf16 h0 = __float2bfloat16(f[2*j]);
        bf16 h1 = __float2bfloat16(f[2*j+1]);
        float l0 = f[2*j]   - __bfloat162float(h0);
        float l1 = f[2*j+1] - __bfloat162float(h1);
        bf162 hh = __halves2bfloat162(h0, h1);
        hw[j] = *reinterpret_cast<uint32_t*>(&hh);
        lw[j] = packbf2(l0, l1);
    }
    ((uint4*)xh)[i] = make_uint4(hw[0], hw[1], hw[2], hw[3]);
    ((uint4*)xl)[i] = make_uint4(lw[0], lw[1], lw[2], lw[3]);
}
__global__ __launch_bounds__(256) void cvt_w3(const float* __restrict__ Wq,
                                              const float* __restrict__ Wk,
                                              const float* __restrict__ Wv) {
    const int which = blockIdx.y;
    const float* W = (which == 0) ? Wq : (which == 1) ? Wk : Wv;
    bf16* wh = g_whi + (size_t)which * (NN * DD);
    bf16* wl = g_wlo + (size_t)which * (NN * DD);
    int idx = blockIdx.x * 256 + threadIdx.x;
    float4 wv = ((const float4*)W)[idx];
    int a4 = idx & 15;
    int d  = (idx >> 4) & 1023;
    int h  = idx >> 14;
    int nb = h * AA + a4 * 4;
    float vals[4] = {wv.x, wv.y, wv.z, wv.w};
    #pragma unroll
    for (int j = 0; j < 4; j++) {
        bf16 hi = __float2bfloat16(vals[j]);
        bf16 lo = __float2bfloat16(vals[j] - __bfloat162float(hi));
        size_t o = (size_t)(nb + j) * DD + d;
        wh[o] = hi;
        wl[o] = lo;
    }
}

// ======================= projection GEMM =======================
// block tile 128x128, 256 threads, warps 4(m) x 2(n), warp tile 32x64.
// 3-stage cp.async ring, issue-2-ahead, ONE barrier per K-chunk.
// hi tiles padded (80B rows); lo tiles unpadded 64B rows with SW64 swizzle (conflict-free).
#define KC 32
#define XPHB 80                                // hi row pitch, bytes
#define POFF_WH 10240                          // Whi after Xhi (128*80)
#define POFF_XL 20480                          // Xlo (swizzled, 128*64)
#define POFF_WL 28672                          // Wlo (swizzled)
#define PSTG_B 36864                           // stage bytes
#define PROJ_SMEM (3*PSTG_B)                   // 110592

__global__ __launch_bounds__(256, 2) void proj_mma(const float* __restrict__ bq,
                                                   const float* __restrict__ bk,
                                                   const float* __restrict__ bv) {
    const int which = blockIdx.z;
    const float* bias = (which == 0) ? bq : (which == 1) ? bk : bv;
    const bf16* Xh = g_xhi + (size_t)which * BSD;
    const bf16* Xl = g_xlo + (size_t)which * BSD;
    const bf16* Wh = g_whi + (size_t)which * (NN * DD);
    const bf16* Wl = g_wlo + (size_t)which * (NN * DD);
    extern __shared__ bf16 sm[];
    const int t = threadIdx.x, lane = t & 31, wid = t >> 5;
    const int wm = wid & 3, wn = wid >> 2;
    const int r0 = blockIdx.x * 128, n0 = blockIdx.y * 128;
    const uint32_t sbase = smem_u32(sm);

    float c[2][8][4];
    #pragma unroll
    for (int mt = 0; mt < 2; mt++)
        #pragma unroll
        for (int nt = 0; nt < 8; nt++)
            #pragma unroll
            for (int i = 0; i < 4; i++) c[mt][nt][i] = 0.0f;

    // 8 cp.async of 16B per thread per chunk
#define PROJ_ISSUE(kc_) do {                                                       \
    int k0_ = (kc_) * KC;                                                          \
    uint32_t stg_ = sbase + ((kc_) % 3) * PSTG_B;                                  \
    _Pragma("unroll")                                                              \
    for (int i = 0; i < 8; i++) {                                                  \
        int rem = ((i & 1) << 8) + t; int row = rem >> 2, cq = rem & 3;            \
        const bf16* src;  uint32_t dst;                                            \
        uint32_t osw = SW64((uint32_t)(row * 64 + cq * 16));                       \
        if      ((i >> 1) == 0) { src = Xh + (size_t)(r0 + row) * DD + k0_ + cq * 8; \
                                  dst = stg_ + row * XPHB + cq * 16; }             \
        else if ((i >> 1) == 1) { src = Wh + (size_t)(n0 + row) * DD + k0_ + cq * 8; \
                                  dst = stg_ + POFF_WH + row * XPHB + cq * 16; }   \
        else if ((i >> 1) == 2) { src = Xl + (size_t)(r0 + row) * DD + k0_ + cq * 8; \
                                  dst = stg_ + POFF_XL + osw; }                    \
        else                    { src = Wl + (size_t)(n0 + row) * DD + k0_ + cq * 8; \
                                  dst = stg_ + POFF_WL + osw; }                    \
        CPA16(dst, src);                                                           \
    } } while (0)

    PROJ_ISSUE(0);
    CPA_COMMIT();
    PROJ_ISSUE(1);
    CPA_COMMIT();
    #pragma unroll 1
    for (int kc = 0; kc < DD / KC; kc++) {
        if (kc + 1 < DD / KC) CPA_WAIT(1); else CPA_WAIT(0);
        __syncthreads();   // stage kc%3 ready; all prior reads of stage (kc-1)%3 complete
        if (kc + 2 < DD / KC) {
            PROJ_ISSUE(kc + 2);    // writes stage (kc-1)%3 — safe after barrier
            CPA_COMMIT();
        }

        const uint32_t stage = sbase + (kc % 3) * PSTG_B;
        #pragma unroll
        for (int ka = 0; ka < 2; ka++) {
            uint32_t xh[2][4], xl[2][4];
            #pragma unroll
            for (int mt = 0; mt < 2; mt++) {
                int arow = wm * 32 + mt * 16 + (lane & 15);
                int acolB = ka * 32 + (lane >> 4) * 16;
                ldsm4(xh[mt], stage + arow * XPHB + acolB);
                ldsm4(xl[mt], stage + POFF_XL + SW64((uint32_t)(arow * 64 + acolB)));
            }
            #pragma unroll
            for (int jp = 0; jp < 4; jp++) {
                uint32_t wh[4], wl[4];
                int brow = wn * 64 + jp * 16 + (lane & 7) + ((lane & 16) ? 8 : 0);
                int bcolB = ka * 32 + ((lane >> 3) & 1) * 16;
                ldsm4(wh, stage + POFF_WH + brow * XPHB + bcolB);
                ldsm4(wl, stage + POFF_WL + SW64((uint32_t)(brow * 64 + bcolB)));
                #pragma unroll
                for (int mt = 0; mt < 2; mt++) {
                    mma16816(c[mt][2*jp],   xh[mt], &wh[0]);
                    mma16816(c[mt][2*jp],   xh[mt], &wl[0]);
                    mma16816(c[mt][2*jp],   xl[mt], &wh[0]);
                    mma16816(c[mt][2*jp+1], xh[mt], &wh[2]);
                    mma16816(c[mt][2*jp+1], xh[mt], &wl[2]);
                    mma16816(c[mt][2*jp+1], xl[mt], &wh[2]);
                }
            }
        }
    }

    // epilogue
    const int g = lane >> 2, l = lane & 3;
    #pragma unroll
    for (int mt = 0; mt < 2; mt++) {
        int row = r0 + wm * 32 + mt * 16 + g;
        int b = row >> 11, s = row & (SS - 1);
        #pragma unroll
        for (int nt = 0; nt < 8; nt++) {
            int n = n0 + wn * 64 + nt * 8 + l * 2;
            int h = n >> 6, a = n & 63;
            size_t off = ((size_t)(b * HH + h) * SS + s) * AA + a;
            float bv0 = bias[n], bv1 = bias[n + 1];
            float p0 = c[mt][nt][0] + bv0, p1 = c[mt][nt][1] + bv1;
            float p2 = c[mt][nt][2] + bv0, p3 = c[mt][nt][3] + bv1;
            if (which == 2) {
                *(uint32_t*)(g_vh2 + off)          = packh2(p0, p1);
                *(uint32_t*)(g_vh2 + off + 8 * AA) = packh2(p2, p3);
            } else {
                bf16 *outhi = (which == 0) ? g_qhi : g_khi;
                bf16 *outlo = (which == 0) ? g_qlo : g_klo;
                uint32_t hi, lo;
                split2(p0, p1, hi, lo);
                *(uint32_t*)(outhi + off) = hi;
                *(uint32_t*)(outlo + off) = lo;
                split2(p2, p3, hi, lo);
                *(uint32_t*)(outhi + off + 8 * AA) = hi;
                *(uint32_t*)(outlo + off + 8 * AA) = lo;
            }
        }
    }
}

// ======================= flash attention (identical to R8 best) =======================
#define QP 72
#define ASTG_H (3*64*QP)                       // Khi, Klo, V
#define ASTG_B (ASTG_H*2)                      // 27648 bytes
#define OFF_QL (128*QP*2)
#define OFF_ST (256*QP*2)                      // 36864
#define ATTN_SMEM (OFF_ST + 2*ASTG_B)          // 92160 bytes

__global__ __launch_bounds__(256, 2) void attn_mma(float* __restrict__ out) {
    extern __shared__ bf16 smh[];
    bf16* Qh = smh;
    bf16* Ql = Qh + 128 * QP;

    const int bh = blockIdx.y, q0 = blockIdx.x * 128;
    const int t = threadIdx.x, lane = t & 31, wid = t >> 5;
    const int m0w = wid * 16;
    const size_t bhoff = (size_t)bh * SS * AA;
    const uint32_t sb = smem_u32(smh);

#define ATTN_ISSUE(kt_) do {                                                      \
    const size_t toff_ = bhoff + (size_t)(kt_) * 64 * AA;                         \
    uint32_t stg_ = sb + OFF_ST + ((kt_) & 1) * ASTG_B;                           \
    _Pragma("unroll")                                                             \
    for (int i = 0; i < 2; i++) {                                                 \
        int idx = t + i * 256; int row = idx >> 3, cq = idx & 7;                  \
        uint32_t so = stg_ + (row * QP + cq * 8) * 2;                             \
        size_t go = toff_ + row * AA + cq * 8;                                    \
        CPA16(so,              g_khi + go);                                       \
        CPA16(so + 64*QP*2,    g_klo + go);                                       \
        CPA16(so + 128*QP*2,   g_vh2 + go);                                       \
    } } while (0)

    {
        const bf16* Qghi = g_qhi + bhoff + (size_t)q0 * AA;
        const bf16* Qglo = g_qlo + bhoff + (size_t)q0 * AA;
        #pragma unroll
        for (int i = 0; i < 4; i++) {
            int idx = t + i * 256;
            int row = idx >> 3, cq = idx & 7;
            *(uint4*)(Qh + row * QP + cq * 8) = *(const uint4*)(Qghi + row * AA + cq * 8);
            *(uint4*)(Ql + row * QP + cq * 8) = *(const uint4*)(Qglo + row * AA + cq * 8);
        }
    }

    ATTN_ISSUE(0);
    CPA_COMMIT();

    float o[8][4];
    float ls[4] = {0.0f, 0.0f, 0.0f, 0.0f};
    #pragma unroll
    for (int j = 0; j < 8; j++)
        #pragma unroll
        for (int i = 0; i < 4; i++) o[j][i] = 0.0f;
    float mi0 = -INFINITY, mi1 = -INFINITY;
    const uint32_t onesb[2] = {ONESH2, ONESH2};

    #pragma unroll 1
    for (int kt = 0; kt < SS / 64; kt++) {
        if (kt + 1 < SS / 64) {
            ATTN_ISSUE(kt + 1);
            CPA_COMMIT();
            CPA_WAIT(1);
        } else {
            CPA_WAIT(0);
        }
        __syncthreads();
        const uint32_t stg = sb + OFF_ST + (kt & 1) * ASTG_B;

        float s[8][4];
        #pragma unroll
        for (int j = 0; j < 8; j++)
            #pragma unroll
            for (int i = 0; i < 4; i++) s[j][i] = 0.0f;

        #pragma unroll
        for (int ka = 0; ka < 4; ka++) {
            const int a0 = ka * 16;
            uint32_t qh[4], ql[4];
            uint32_t qaddr = sb + ((m0w + (lane & 15)) * QP + a0 + (lane >> 4) * 8) * 2;
            ldsm4(qh, qaddr);
            ldsm4(ql, qaddr + OFF_QL);
            #pragma unroll
            for (int jp = 0; jp < 4; jp++) {
                uint32_t kh4[4], kl4[4];
                int krow = jp * 16 + (lane & 7) + ((lane & 16) ? 8 : 0);
                uint32_t kaddr = stg + (krow * QP + a0 + ((lane >> 3) & 1) * 8) * 2;
                ldsm4(kh4, kaddr);
                ldsm4(kl4, kaddr + 64 * QP * 2);
                mma16816(s[2*jp],   qh, &kh4[0]);
                mma16816(s[2*jp],   qh, &kl4[0]);
                mma16816(s[2*jp],   ql, &kh4[0]);
                mma16816(s[2*jp+1], qh, &kh4[2]);
                mma16816(s[2*jp+1], qh, &kl4[2]);
                mma16816(s[2*jp+1], ql, &kh4[2]);
            }
        }

        float tm0 = -INFINITY, tm1 = -INFINITY;
        #pragma unroll
        for (int j = 0; j < 8; j++) {
            tm0 = fmaxf(tm0, fmaxf(s[j][0], s[j][1]));
            tm1 = fmaxf(tm1, fmaxf(s[j][2], s[j][3]));
        }
        tm0 = fmaxf(tm0, __shfl_xor_sync(0xffffffffu, tm0, 1));
        tm0 = fmaxf(tm0, __shfl_xor_sync(0xffffffffu, tm0, 2));
        tm1 = fmaxf(tm1, __shfl_xor_sync(0xffffffffu, tm1, 1));
        tm1 = fmaxf(tm1, __shfl_xor_sync(0xffffffffu, tm1, 2));
        float mn0 = fmaxf(mi0, tm0), mn1 = fmaxf(mi1, tm1);
        if (tm0 > mi0 || tm1 > mi1) {
            float corr0 = ex2f((mi0 - mn0) * L2E);
            float corr1 = ex2f((mi1 - mn1) * L2E);
            #pragma unroll
            for (int j = 0; j < 8; j++) {
                o[j][0] *= corr0; o[j][1] *= corr0;
                o[j][2] *= corr1; o[j][3] *= corr1;
            }
            ls[0] *= corr0; ls[1] *= corr0; ls[2] *= corr1; ls[3] *= corr1;
            mi0 = mn0; mi1 = mn1;
        }
        const float b0 = -mi0 * L2E, b1 = -mi1 * L2E;
        uint32_t ps[8][2];
        #pragma unroll
        for (int j = 0; j < 8; j++) {
            ps[j][0] = ex2h2(packh2(fmaf(s[j][0], L2E, b0), fmaf(s[j][1], L2E, b0)));
            ps[j][1] = ex2h2(packh2(fmaf(s[j][2], L2E, b1), fmaf(s[j][3], L2E, b1)));
        }

        #pragma unroll
        for (int kc = 0; kc < 4; kc++) {
            uint32_t pa[4];
            pa[0] = ps[2*kc][0];
            pa[1] = ps[2*kc][1];
            pa[2] = ps[2*kc+1][0];
            pa[3] = ps[2*kc+1][1];
            mma16816h(ls, pa, onesb);
            #pragma unroll
            for (int jp = 0; jp < 4; jp++) {
                uint32_t vh4[4];
                int vrow = kc * 16 + (lane & 7) + ((lane >> 3) & 1) * 8;
                uint32_t vaddr = stg + 128 * QP * 2 +
                    (vrow * QP + jp * 16 + ((lane & 16) ? 8 : 0)) * 2;
                ldsm4t(vh4, vaddr);
                mma16816h(o[2*jp],   pa, &vh4[0]);
                mma16816h(o[2*jp+1], pa, &vh4[2]);
            }
        }
        __syncthreads();
    }

    const float inv0 = 1.0f / ls[0], inv1 = 1.0f / ls[2];
    const int g = lane >> 2, l = lane & 3;
    const int b = bh >> 4, h = bh & 15;
    const int row0 = q0 + m0w + g;
    float* outp = out + ((size_t)b * SS + row0) * NN + h * AA;
    #pragma unroll
    for (int j = 0; j < 8; j++) {
        float2 w0 = make_float2(o[j][0] * inv0, o[j][1] * inv0);
        float2 w1 = make_float2(o[j][2] * inv1, o[j][3] * inv1);
        *(float2*)(outp + j * 8 + l * 2) = w0;
        *(float2*)(outp + (size_t)8 * NN + j * 8 + l * 2) = w1;
    }
}

extern "C" void kernel_launch(void* const* d_in, const int* in_sizes, int n_in,
                              void* d_out, int out_size) {
    (void)in_sizes; (void)n_in; (void)out_size;
    const float* q  = (const float*)d_in[0];
    const float* k  = (const float*)d_in[1];
    const float* v  = (const float*)d_in[2];
    const float* Wq = (const float*)d_in[3];
    const float* bq = (const float*)d_in[4];
    const float* Wk = (const float*)d_in[5];
    const float* bk = (const float*)d_in[6];
    const float* Wv = (const float*)d_in[7];
    const float* bv = (const float*)d_in[8];
    float* out = (float*)d_out;

    cudaFuncSetAttribute(proj_mma, cudaFuncAttributeMaxDynamicSharedMemorySize, PROJ_SMEM);
    cudaFuncSetAttribute(attn_mma, cudaFuncAttributeMaxDynamicSharedMemorySize, ATTN_SMEM);

    cvt_x3<<<dim3(4096, 3), 256>>>(q, k, v);
    cvt_w3<<<dim3(1024, 3), 256>>>(Wq, Wk, Wv);
    proj_mma<<<dim3(64, 8, 3), 256, PROJ_SMEM>>>(bq, bk, bv);

    dim3 ag(SS / 128, BB * HH);
    attn_mma<<<ag, 256, ATTN_SMEM>>>(out);
}

// round 12
// speedup vs baseline: 1.0872x; 1.0265x over previous
#include <cuda_runtime.h>
#include <cuda_bf16.h>
#include <cuda_fp16.h>
#include <math.h>
#include <stdint.h>

#define BB 4
#define SS 2048
#define DD 1024
#define HH 16
#define AA 64
#define NN (HH*AA)   // 1024
#define BSD (BB*SS*DD)

typedef __nv_bfloat16 bf16;
typedef __nv_bfloat162 bf162;

// ---- scratch ----
__device__ bf16 g_qhi[BB*HH*SS*AA];
__device__ bf16 g_qlo[BB*HH*SS*AA];
__device__ bf16 g_khi[BB*HH*SS*AA];
__device__ bf16 g_klo[BB*HH*SS*AA];
__device__ __half g_vh2[BB*HH*SS*AA];        // V single fp16
__device__ bf16 g_xhi[3*BSD];
__device__ bf16 g_xlo[3*BSD];
__device__ bf16 g_whi[3*NN*DD];
__device__ bf16 g_wlo[3*NN*DD];

// ======================= helpers =======================
__device__ __forceinline__ uint32_t smem_u32(const void* p) {
    uint32_t a;
    asm("{ .reg .u64 t; cvta.to.shared.u64 t, %1; cvt.u32.u64 %0, t; }" : "=r"(a) : "l"(p));
    return a;
}
__device__ __forceinline__ void mma16816(float* c, const uint32_t* a, const uint32_t* b) {
    asm volatile(
        "mma.sync.aligned.m16n8k16.row.col.f32.bf16.bf16.f32 "
        "{%0,%1,%2,%3}, {%4,%5,%6,%7}, {%8,%9}, {%0,%1,%2,%3};"
        : "+f"(c[0]), "+f"(c[1]), "+f"(c[2]), "+f"(c[3])
        : "r"(a[0]), "r"(a[1]), "r"(a[2]), "r"(a[3]), "r"(b[0]), "r"(b[1]));
}
__device__ __forceinline__ void mma16816h(float* c, const uint32_t* a, const uint32_t* b) {
    asm volatile(
        "mma.sync.aligned.m16n8k16.row.col.f32.f16.f16.f32 "
        "{%0,%1,%2,%3}, {%4,%5,%6,%7}, {%8,%9}, {%0,%1,%2,%3};"
        : "+f"(c[0]), "+f"(c[1]), "+f"(c[2]), "+f"(c[3])
        : "r"(a[0]), "r"(a[1]), "r"(a[2]), "r"(a[3]), "r"(b[0]), "r"(b[1]));
}
__device__ __forceinline__ void ldsm4(uint32_t* r, uint32_t addr) {
    asm volatile("ldmatrix.sync.aligned.m8n8.x4.shared.b16 {%0,%1,%2,%3}, [%4];"
        : "=r"(r[0]), "=r"(r[1]), "=r"(r[2]), "=r"(r[3]) : "r"(addr));
}
__device__ __forceinline__ void ldsm4t(uint32_t* r, uint32_t addr) {
    asm volatile("ldmatrix.sync.aligned.m8n8.x4.trans.shared.b16 {%0,%1,%2,%3}, [%4];"
        : "=r"(r[0]), "=r"(r[1]), "=r"(r[2]), "=r"(r[3]) : "r"(addr));
}
#define CPA16(dst_u32, src_ptr) \
    asm volatile("cp.async.cg.shared.global [%0], [%1], 16;" :: "r"(dst_u32), "l"(src_ptr))
#define CPA_COMMIT() asm volatile("cp.async.commit_group;" ::: "memory")
#define CPA_WAIT(n)  asm volatile("cp.async.wait_group %0;" :: "n"(n) : "memory")

__device__ __forceinline__ float ex2f(float x) {
    float r;
    asm("ex2.approx.f32 %0, %1;" : "=f"(r) : "f"(x));
    return r;
}
__device__ __forceinline__ uint32_t ex2h2(uint32_t a) {
    uint32_t r;
    asm("ex2.approx.f16x2 %0, %1;" : "=r"(r) : "r"(a));
    return r;
}
__device__ __forceinline__ uint32_t packh2(float a, float b) {
    __half2 h = __floats2half2_rn(a, b);      // x = a (low), y = b (high)
    return *reinterpret_cast<uint32_t*>(&h);
}
__device__ __forceinline__ uint32_t packbf2(float a, float b) {
    bf162 h = __floats2bfloat162_rn(a, b);
    return *reinterpret_cast<uint32_t*>(&h);
}
__device__ __forceinline__ void split2(float p0, float p1, uint32_t& hi, uint32_t& lo) {
    bf162 h = __floats2bfloat162_rn(p0, p1);
    bf162 l = __floats2bfloat162_rn(p0 - __bfloat162float(h.x), p1 - __bfloat162float(h.y));
    hi = *reinterpret_cast<uint32_t*>(&h);
    lo = *reinterpret_cast<uint32_t*>(&l);
}
#define L2E 1.4426950408889634f
#define ONESH2 0x3C003C00u                    // fp16 (1.0, 1.0)
#define SW64(o) ((o) ^ (((o) >> 3) & 0x30))   // conflict-free swizzle for 64B rows
#define SWC(colB, row) ((uint32_t)((colB) ^ (((row) & 7) << 4)))  // 128B-row swizzle, closed form

// ======================= conversion kernels (fused over q,k,v) =======================
__global__ __launch_bounds__(256) void cvt_x3(const float* __restrict__ q,
                                              const float* __restrict__ k,
                                              const float* __restrict__ v) {
    const int which = blockIdx.y;
    const float* X = (which == 0) ? q : (which == 1) ? k : v;
    bf16* xh = g_xhi + (size_t)which * BSD;
    bf16* xl = g_xlo + (size_t)which * BSD;
    int i = blockIdx.x * 256 + threadIdx.x;    // 0..BSD/8-1
    float4 a = ((const float4*)X)[2*i];
    float4 b = ((const float4*)X)[2*i+1];
    float f[8] = {a.x, a.y, a.z, a.w, b.x, b.y, b.z, b.w};
    uint32_t hw[4], lw[4];
    #pragma unroll
    for (int j = 0; j < 4; j++) {
        bf16 h0 = __float2bfloat16(f[2*j]);
        bf16 h1 = __float2bfloat16(f[2*j+1]);
        float l0 = f[2*j]   - __bfloat162float(h0);
        float l1 = f[2*j+1] - __bfloat162float(h1);
        bf162 hh = __halves2bfloat162(h0, h1);
        hw[j] = *reinterpret_cast<uint32_t*>(&hh);
        lw[j] = packbf2(l0, l1);
    }
    ((uint4*)xh)[i] = make_uint4(hw[0], hw[1], hw[2], hw[3]);
    ((uint4*)xl)[i] = make_uint4(lw[0], lw[1], lw[2], lw[3]);
}
__global__ __launch_bounds__(256) void cvt_w3(const float* __restrict__ Wq,
                                              const float* __restrict__ Wk,
                                              const float* __restrict__ Wv) {
    const int which = blockIdx.y;
    const float* W = (which == 0) ? Wq : (which == 1) ? Wk : Wv;
    bf16* wh = g_whi + (size_t)which * (NN * DD);
    bf16* wl = g_wlo + (size_t)which * (NN * DD);
    int idx = blockIdx.x * 256 + threadIdx.x;
    float4 wv = ((const float4*)W)[idx];
    int a4 = idx & 15;
    int d  = (idx >> 4) & 1023;
    int h  = idx >> 14;
    int nb = h * AA + a4 * 4;
    float vals[4] = {wv.x, wv.y, wv.z, wv.w};
    #pragma unroll
    for (int j = 0; j < 4; j++) {
        bf16 hi = __float2bfloat16(vals[j]);
        bf16 lo = __float2bfloat16(vals[j] - __bfloat162float(hi));
        size_t o = (size_t)(nb + j) * DD + d;
        wh[o] = hi;
        wl[o] = lo;
    }
}

// ======================= projection GEMM (identical to R11 best) =======================
#define KC 32
#define XPHB 80                                // hi row pitch, bytes
#define POFF_WH 10240                          // Whi after Xhi (128*80)
#define POFF_XL 20480                          // Xlo (swizzled, 128*64)
#define POFF_WL 28672                          // Wlo (swizzled)
#define PSTG_B 36864                           // stage bytes
#define PROJ_SMEM (3*PSTG_B)                   // 110592

__global__ __launch_bounds__(256, 2) void proj_mma(const float* __restrict__ bq,
                                                   const float* __restrict__ bk,
                                                   const float* __restrict__ bv) {
    const int which = blockIdx.z;
    const float* bias = (which == 0) ? bq : (which == 1) ? bk : bv;
    const bf16* Xh = g_xhi + (size_t)which * BSD;
    const bf16* Xl = g_xlo + (size_t)which * BSD;
    const bf16* Wh = g_whi + (size_t)which * (NN * DD);
    const bf16* Wl = g_wlo + (size_t)which * (NN * DD);
    extern __shared__ bf16 sm[];
    const int t = threadIdx.x, lane = t & 31, wid = t >> 5;
    const int wm = wid & 3, wn = wid >> 2;
    const int r0 = blockIdx.x * 128, n0 = blockIdx.y * 128;
    const uint32_t sbase = smem_u32(sm);

    float c[2][8][4];
    #pragma unroll
    for (int mt = 0; mt < 2; mt++)
        #pragma unroll
        for (int nt = 0; nt < 8; nt++)
            #pragma unroll
            for (int i = 0; i < 4; i++) c[mt][nt][i] = 0.0f;

#define PROJ_ISSUE(kc_) do {                                                       \
    int k0_ = (kc_) * KC;                                                          \
    uint32_t stg_ = sbase + ((kc_) % 3) * PSTG_B;                                  \
    _Pragma("unroll")                                                              \
    for (int i = 0; i < 8; i++) {                                                  \
        int rem = ((i & 1) << 8) + t; int row = rem >> 2, cq = rem & 3;            \
        const bf16* src;  uint32_t dst;                                            \
        uint32_t osw = SW64((uint32_t)(row * 64 + cq * 16));                       \
        if      ((i >> 1) == 0) { src = Xh + (size_t)(r0 + row) * DD + k0_ + cq * 8; \
                                  dst = stg_ + row * XPHB + cq * 16; }             \
        else if ((i >> 1) == 1) { src = Wh + (size_t)(n0 + row) * DD + k0_ + cq * 8; \
                                  dst = stg_ + POFF_WH + row * XPHB + cq * 16; }   \
        else if ((i >> 1) == 2) { src = Xl + (size_t)(r0 + row) * DD + k0_ + cq * 8; \
                                  dst = stg_ + POFF_XL + osw; }                    \
        else                    { src = Wl + (size_t)(n0 + row) * DD + k0_ + cq * 8; \
                                  dst = stg_ + POFF_WL + osw; }                    \
        CPA16(dst, src);                                                           \
    } } while (0)

    PROJ_ISSUE(0);
    CPA_COMMIT();
    PROJ_ISSUE(1);
    CPA_COMMIT();
    #pragma unroll 1
    for (int kc = 0; kc < DD / KC; kc++) {
        if (kc + 1 < DD / KC) CPA_WAIT(1); else CPA_WAIT(0);
        __syncthreads();
        if (kc + 2 < DD / KC) {
            PROJ_ISSUE(kc + 2);
            CPA_COMMIT();
        }

        const uint32_t stage = sbase + (kc % 3) * PSTG_B;
        #pragma unroll
        for (int ka = 0; ka < 2; ka++) {
            uint32_t xh[2][4], xl[2][4];
            #pragma unroll
            for (int mt = 0; mt < 2; mt++) {
                int arow = wm * 32 + mt * 16 + (lane & 15);
                int acolB = ka * 32 + (lane >> 4) * 16;
                ldsm4(xh[mt], stage + arow * XPHB + acolB);
                ldsm4(xl[mt], stage + POFF_XL + SW64((uint32_t)(arow * 64 + acolB)));
            }
            #pragma unroll
            for (int jp = 0; jp < 4; jp++) {
                uint32_t wh[4], wl[4];
                int brow = wn * 64 + jp * 16 + (lane & 7) + ((lane & 16) ? 8 : 0);
                int bcolB = ka * 32 + ((lane >> 3) & 1) * 16;
                ldsm4(wh, stage + POFF_WH + brow * XPHB + bcolB);
                ldsm4(wl, stage + POFF_WL + SW64((uint32_t)(brow * 64 + bcolB)));
                #pragma unroll
                for (int mt = 0; mt < 2; mt++) {
                    mma16816(c[mt][2*jp],   xh[mt], &wh[0]);
                    mma16816(c[mt][2*jp],   xh[mt], &wl[0]);
                    mma16816(c[mt][2*jp],   xl[mt], &wh[0]);
                    mma16816(c[mt][2*jp+1], xh[mt], &wh[2]);
                    mma16816(c[mt][2*jp+1], xh[mt], &wl[2]);
                    mma16816(c[mt][2*jp+1], xl[mt], &wh[2]);
                }
            }
        }
    }

    // epilogue
    const int g = lane >> 2, l = lane & 3;
    #pragma unroll
    for (int mt = 0; mt < 2; mt++) {
        int row = r0 + wm * 32 + mt * 16 + g;
        int b = row >> 11, s = row & (SS - 1);
        #pragma unroll
        for (int nt = 0; nt < 8; nt++) {
            int n = n0 + wn * 64 + nt * 8 + l * 2;
            int h = n >> 6, a = n & 63;
            size_t off = ((size_t)(b * HH + h) * SS + s) * AA + a;
            float bv0 = bias[n], bv1 = bias[n + 1];
            float p0 = c[mt][nt][0] + bv0, p1 = c[mt][nt][1] + bv1;
            float p2 = c[mt][nt][2] + bv0, p3 = c[mt][nt][3] + bv1;
            if (which == 2) {
                *(uint32_t*)(g_vh2 + off)          = packh2(p0, p1);
                *(uint32_t*)(g_vh2 + off + 8 * AA) = packh2(p2, p3);
            } else {
                bf16 *outhi = (which == 0) ? g_qhi : g_khi;
                bf16 *outlo = (which == 0) ? g_qlo : g_klo;
                uint32_t hi, lo;
                split2(p0, p1, hi, lo);
                *(uint32_t*)(outhi + off) = hi;
                *(uint32_t*)(outlo + off) = lo;
                split2(p2, p3, hi, lo);
                *(uint32_t*)(outhi + off + 8 * AA) = hi;
                *(uint32_t*)(outlo + off + 8 * AA) = lo;
            }
        }
    }
}

// ======================= flash attention =======================
// 3-stage K/V ring, ONE barrier per tile. Unpadded 128B rows + SWC swizzle.
// Layout: Qhi[0,16384) Qlo[16384,32768) then 3 stages of {Kh 8K, Kl 8K, V 8K}.
#define AOFF_QL 16384
#define AOFF_ST 32768
#define ASTG3_B 24576
#define AOFF_KL 8192
#define AOFF_V  16384
#define ATTN_SMEM (AOFF_ST + 3*ASTG3_B)        // 106496 bytes
#define NT (SS/64)

__global__ __launch_bounds__(256, 2) void attn_mma(float* __restrict__ out) {
    extern __shared__ char smc[];

    const int bh = blockIdx.y, q0 = blockIdx.x * 128;
    const int t = threadIdx.x, lane = t & 31, wid = t >> 5;
    const int m0w = wid * 16;
    const size_t bhoff = (size_t)bh * SS * AA;
    const uint32_t sb = smem_u32(smc);

#define ATTN_ISSUE(kt_) do {                                                      \
    const size_t toff_ = bhoff + (size_t)(kt_) * 64 * AA;                         \
    uint32_t stg_ = sb + AOFF_ST + ((kt_) % 3) * ASTG3_B;                         \
    _Pragma("unroll")                                                             \
    for (int i = 0; i < 2; i++) {                                                 \
        int idx = t + i * 256; int row = idx >> 3, cq = idx & 7;                  \
        uint32_t so = stg_ + row * 128 + SWC(cq * 16, row);                       \
        size_t go = toff_ + row * AA + cq * 8;                                    \
        CPA16(so,             g_khi + go);                                        \
        CPA16(so + AOFF_KL,   g_klo + go);                                        \
        CPA16(so + AOFF_V,    g_vh2 + go);                                        \
    } } while (0)

    // load Q hi/lo (swizzled 128B rows)
    {
        const bf16* Qghi = g_qhi + bhoff + (size_t)q0 * AA;
        const bf16* Qglo = g_qlo + bhoff + (size_t)q0 * AA;
        #pragma unroll
        for (int i = 0; i < 4; i++) {
            int idx = t + i * 256;
            int row = idx >> 3, cq = idx & 7;
            uint32_t off = row * 128 + SWC(cq * 16, row);
            *(uint4*)(smc + off)           = *(const uint4*)(Qghi + row * AA + cq * 8);
            *(uint4*)(smc + AOFF_QL + off) = *(const uint4*)(Qglo + row * AA + cq * 8);
        }
    }

    ATTN_ISSUE(0);
    CPA_COMMIT();
    ATTN_ISSUE(1);
    CPA_COMMIT();

    float o[8][4];
    float ls[4] = {0.0f, 0.0f, 0.0f, 0.0f};
    #pragma unroll
    for (int j = 0; j < 8; j++)
        #pragma unroll
        for (int i = 0; i < 4; i++) o[j][i] = 0.0f;
    float mi0 = -INFINITY, mi1 = -INFINITY;
    const uint32_t onesb[2] = {ONESH2, ONESH2};

    #pragma unroll 1
    for (int kt = 0; kt < NT; kt++) {
        if (kt + 1 < NT) CPA_WAIT(1); else CPA_WAIT(0);
        __syncthreads();   // stage kt%3 ready; all reads of stage (kt-1)%3 complete
        if (kt + 2 < NT) {
            ATTN_ISSUE(kt + 2);    // writes stage (kt-1)%3 — safe after barrier
            CPA_COMMIT();
        }
        const uint32_t stg = sb + AOFF_ST + (kt % 3) * ASTG3_B;

        // ---- S = Q K^T, bf16 3-term split
        float s[8][4];
        #pragma unroll
        for (int j = 0; j < 8; j++)
            #pragma unroll
            for (int i = 0; i < 4; i++) s[j][i] = 0.0f;

        #pragma unroll
        for (int ka = 0; ka < 4; ka++) {
            uint32_t qh[4], ql[4];
            int qrow = m0w + (lane & 15);
            int qcolB = ka * 32 + (lane >> 4) * 16;
            uint32_t qaddr = sb + qrow * 128 + SWC(qcolB, qrow);
            ldsm4(qh, qaddr);
            ldsm4(ql, qaddr + AOFF_QL);
            #pragma unroll
            for (int jp = 0; jp < 4; jp++) {
                uint32_t kh4[4], kl4[4];
                int krow = jp * 16 + (lane & 7) + ((lane & 16) ? 8 : 0);
                int kcolB = ka * 32 + ((lane >> 3) & 1) * 16;
                uint32_t kaddr = stg + krow * 128 + SWC(kcolB, krow);
                ldsm4(kh4, kaddr);
                ldsm4(kl4, kaddr + AOFF_KL);
                mma16816(s[2*jp],   qh, &kh4[0]);
                mma16816(s[2*jp],   qh, &kl4[0]);
                mma16816(s[2*jp],   ql, &kh4[0]);
                mma16816(s[2*jp+1], qh, &kh4[2]);
                mma16816(s[2*jp+1], qh, &kl4[2]);
                mma16816(s[2*jp+1], ql, &kh4[2]);
            }
        }

        // ---- online softmax
        float tm0 = -INFINITY, tm1 = -INFINITY;
        #pragma unroll
        for (int j = 0; j < 8; j++) {
            tm0 = fmaxf(tm0, fmaxf(s[j][0], s[j][1]));
            tm1 = fmaxf(tm1, fmaxf(s[j][2], s[j][3]));
        }
        tm0 = fmaxf(tm0, __shfl_xor_sync(0xffffffffu, tm0, 1));
        tm0 = fmaxf(tm0, __shfl_xor_sync(0xffffffffu, tm0, 2));
        tm1 = fmaxf(tm1, __shfl_xor_sync(0xffffffffu, tm1, 1));
        tm1 = fmaxf(tm1, __shfl_xor_sync(0xffffffffu, tm1, 2));
        float mn0 = fmaxf(mi0, tm0), mn1 = fmaxf(mi1, tm1);
        if (tm0 > mi0 || tm1 > mi1) {
            float corr0 = ex2f((mi0 - mn0) * L2E);
            float corr1 = ex2f((mi1 - mn1) * L2E);
            #pragma unroll
            for (int j = 0; j < 8; j++) {
                o[j][0] *= corr0; o[j][1] *= corr0;
                o[j][2] *= corr1; o[j][3] *= corr1;
            }
            ls[0] *= corr0; ls[1] *= corr0; ls[2] *= corr1; ls[3] *= corr1;
            mi0 = mn0; mi1 = mn1;
        }
        const float b0 = -mi0 * L2E, b1 = -mi1 * L2E;
        uint32_t ps[8][2];
        #pragma unroll
        for (int j = 0; j < 8; j++) {
            ps[j][0] = ex2h2(packh2(fmaf(s[j][0], L2E, b0), fmaf(s[j][1], L2E, b0)));
            ps[j][1] = ex2h2(packh2(fmaf(s[j][2], L2E, b1), fmaf(s[j][3], L2E, b1)));
        }

        // ---- O += P V (fp16), row sums via ones-MMA
        #pragma unroll
        for (int kc = 0; kc < 4; kc++) {
            uint32_t pa[4];
            pa[0] = ps[2*kc][0];
            pa[1] = ps[2*kc][1];
            pa[2] = ps[2*kc+1][0];
            pa[3] = ps[2*kc+1][1];
            mma16816h(ls, pa, onesb);
            #pragma unroll
            for (int jp = 0; jp < 4; jp++) {
                uint32_t vh4[4];
                int vrow = kc * 16 + (lane & 7) + ((lane >> 3) & 1) * 8;
                int vcolB = jp * 32 + ((lane & 16) ? 16 : 0);
                uint32_t vaddr = stg + AOFF_V + vrow * 128 + SWC(vcolB, vrow);
                ldsm4t(vh4, vaddr);
                mma16816h(o[2*jp],   pa, &vh4[0]);
                mma16816h(o[2*jp+1], pa, &vh4[2]);
            }
        }
        // no trailing barrier: 3-stage ring + top barrier covers WAR hazards
    }

    // ---- epilogue: normalize by ones-MMA row sums
    const float inv0 = 1.0f / ls[0], inv1 = 1.0f / ls[2];
    const int g = lane >> 2, l = lane & 3;
    const int b = bh >> 4, h = bh & 15;
    const int row0 = q0 + m0w + g;
    float* outp = out + ((size_t)b * SS + row0) * NN + h * AA;
    #pragma unroll
    for (int j = 0; j < 8; j++) {
        float2 w0 = make_float2(o[j][0] * inv0, o[j][1] * inv0);
        float2 w1 = make_float2(o[j][2] * inv1, o[j][3] * inv1);
        *(float2*)(outp + j * 8 + l * 2) = w0;
        *(float2*)(outp + (size_t)8 * NN + j * 8 + l * 2) = w1;
    }
}

extern "C" void kernel_launch(void* const* d_in, const int* in_sizes, int n_in,
                              void* d_out, int out_size) {
    (void)in_sizes; (void)n_in; (void)out_size;
    const float* q  = (const float*)d_in[0];
    const float* k  = (const float*)d_in[1];
    const float* v  = (const float*)d_in[2];
    const float* Wq = (const float*)d_in[3];
    const float* bq = (const float*)d_in[4];
    const float* Wk = (const float*)d_in[5];
    const float* bk = (const float*)d_in[6];
    const float* Wv = (const float*)d_in[7];
    const float* bv = (const float*)d_in[8];
    float* out = (float*)d_out;

    cudaFuncSetAttribute(proj_mma, cudaFuncAttributeMaxDynamicSharedMemorySize, PROJ_SMEM);
    cudaFuncSetAttribute(attn_mma, cudaFuncAttributeMaxDynamicSharedMemorySize, ATTN_SMEM);

    cvt_x3<<<dim3(4096, 3), 256>>>(q, k, v);
    cvt_w3<<<dim3(1024, 3), 256>>>(Wq, Wk, Wv);
    proj_mma<<<dim3(64, 8, 3), 256, PROJ_SMEM>>>(bq, bk, bv);

    dim3 ag(SS / 128, BB * HH);
    attn_mma<<<ag, 256, ATTN_SMEM>>>(out);
}

// round 13
// speedup vs baseline: 1.2288x; 1.1303x over previous
#include <cuda_runtime.h>
#include <cuda_bf16.h>
#include <cuda_fp16.h>
#include <math.h>
#include <stdint.h>

#define BB 4
#define SS 2048
#define DD 1024
#define HH 16
#define AA 64
#define NN (HH*AA)   // 1024
#define BSD (BB*SS*DD)

typedef __nv_bfloat16 bf16;
typedef __nv_bfloat162 bf162;

// ---- scratch ----
__device__ bf16 g_qhi[BB*HH*SS*AA];
__device__ bf16 g_qlo[BB*HH*SS*AA];
__device__ bf16 g_khi[BB*HH*SS*AA];
__device__ bf16 g_klo[BB*HH*SS*AA];
__device__ __half g_vh2[BB*HH*SS*AA];        // V single fp16
__device__ bf16 g_xhi[2*BSD];                // q,k inputs split
__device__ bf16 g_xlo[2*BSD];
__device__ bf16 g_whi[2*NN*DD];
__device__ bf16 g_wlo[2*NN*DD];
__device__ __half g_xf[BSD];                 // v input fp16
__device__ __half g_wf[NN*DD];               // v weight fp16

// ======================= helpers =======================
__device__ __forceinline__ uint32_t smem_u32(const void* p) {
    uint32_t a;
    asm("{ .reg .u64 t; cvta.to.shared.u64 t, %1; cvt.u32.u64 %0, t; }" : "=r"(a) : "l"(p));
    return a;
}
__device__ __forceinline__ void mma16816(float* c, const uint32_t* a, const uint32_t* b) {
    asm volatile(
        "mma.sync.aligned.m16n8k16.row.col.f32.bf16.bf16.f32 "
        "{%0,%1,%2,%3}, {%4,%5,%6,%7}, {%8,%9}, {%0,%1,%2,%3};"
        : "+f"(c[0]), "+f"(c[1]), "+f"(c[2]), "+f"(c[3])
        : "r"(a[0]), "r"(a[1]), "r"(a[2]), "r"(a[3]), "r"(b[0]), "r"(b[1]));
}
__device__ __forceinline__ void mma16816h(float* c, const uint32_t* a, const uint32_t* b) {
    asm volatile(
        "mma.sync.aligned.m16n8k16.row.col.f32.f16.f16.f32 "
        "{%0,%1,%2,%3}, {%4,%5,%6,%7}, {%8,%9}, {%0,%1,%2,%3};"
        : "+f"(c[0]), "+f"(c[1]), "+f"(c[2]), "+f"(c[3])
        : "r"(a[0]), "r"(a[1]), "r"(a[2]), "r"(a[3]), "r"(b[0]), "r"(b[1]));
}
__device__ __forceinline__ void ldsm4(uint32_t* r, uint32_t addr) {
    asm volatile("ldmatrix.sync.aligned.m8n8.x4.shared.b16 {%0,%1,%2,%3}, [%4];"
        : "=r"(r[0]), "=r"(r[1]), "=r"(r[2]), "=r"(r[3]) : "r"(addr));
}
__device__ __forceinline__ void ldsm4t(uint32_t* r, uint32_t addr) {
    asm volatile("ldmatrix.sync.aligned.m8n8.x4.trans.shared.b16 {%0,%1,%2,%3}, [%4];"
        : "=r"(r[0]), "=r"(r[1]), "=r"(r[2]), "=r"(r[3]) : "r"(addr));
}
#define CPA16(dst_u32, src_ptr) \
    asm volatile("cp.async.cg.shared.global [%0], [%1], 16;" :: "r"(dst_u32), "l"(src_ptr))
#define CPA_COMMIT() asm volatile("cp.async.commit_group;" ::: "memory")
#define CPA_WAIT(n)  asm volatile("cp.async.wait_group %0;" :: "n"(n) : "memory")

__device__ __forceinline__ float ex2f(float x) {
    float r;
    asm("ex2.approx.f32 %0, %1;" : "=f"(r) : "f"(x));
    return r;
}
__device__ __forceinline__ uint32_t ex2h2(uint32_t a) {
    uint32_t r;
    asm("ex2.approx.f16x2 %0, %1;" : "=r"(r) : "r"(a));
    return r;
}
__device__ __forceinline__ uint32_t packh2(float a, float b) {
    __half2 h = __floats2half2_rn(a, b);      // x = a (low), y = b (high)
    return *reinterpret_cast<uint32_t*>(&h);
}
__device__ __forceinline__ uint32_t packbf2(float a, float b) {
    bf162 h = __floats2bfloat162_rn(a, b);
    return *reinterpret_cast<uint32_t*>(&h);
}
__device__ __forceinline__ void split2(float p0, float p1, uint32_t& hi, uint32_t& lo) {
    bf162 h = __floats2bfloat162_rn(p0, p1);
    bf162 l = __floats2bfloat162_rn(p0 - __bfloat162float(h.x), p1 - __bfloat162float(h.y));
    hi = *reinterpret_cast<uint32_t*>(&h);
    lo = *reinterpret_cast<uint32_t*>(&l);
}
#define L2E 1.4426950408889634f
#define ONESH2 0x3C003C00u                    // fp16 (1.0, 1.0)
#define SW64(o) ((o) ^ (((o) >> 3) & 0x30))   // conflict-free swizzle for 64B rows
#define SWC(colB, row) ((uint32_t)((colB) ^ (((row) & 7) << 4)))  // 128B-row swizzle

// ======================= conversion kernels =======================
__global__ __launch_bounds__(256) void cvt_x3(const float* __restrict__ q,
                                              const float* __restrict__ k,
                                              const float* __restrict__ v) {
    const int which = blockIdx.y;
    const float* X = (which == 0) ? q : (which == 1) ? k : v;
    int i = blockIdx.x * 256 + threadIdx.x;    // 0..BSD/8-1
    float4 a = ((const float4*)X)[2*i];
    float4 b = ((const float4*)X)[2*i+1];
    float f[8] = {a.x, a.y, a.z, a.w, b.x, b.y, b.z, b.w};
    if (which == 2) {
        uint32_t hw[4];
        #pragma unroll
        for (int j = 0; j < 4; j++) hw[j] = packh2(f[2*j], f[2*j+1]);
        ((uint4*)g_xf)[i] = make_uint4(hw[0], hw[1], hw[2], hw[3]);
        return;
    }
    bf16* xh = g_xhi + (size_t)which * BSD;
    bf16* xl = g_xlo + (size_t)which * BSD;
    uint32_t hw[4], lw[4];
    #pragma unroll
    for (int j = 0; j < 4; j++) {
        bf16 h0 = __float2bfloat16(f[2*j]);
        bf16 h1 = __float2bfloat16(f[2*j+1]);
        float l0 = f[2*j]   - __bfloat162float(h0);
        float l1 = f[2*j+1] - __bfloat162float(h1);
        bf162 hh = __halves2bfloat162(h0, h1);
        hw[j] = *reinterpret_cast<uint32_t*>(&hh);
        lw[j] = packbf2(l0, l1);
    }
    ((uint4*)xh)[i] = make_uint4(hw[0], hw[1], hw[2], hw[3]);
    ((uint4*)xl)[i] = make_uint4(lw[0], lw[1], lw[2], lw[3]);
}
__global__ __launch_bounds__(256) void cvt_w3(const float* __restrict__ Wq,
                                              const float* __restrict__ Wk,
                                              const float* __restrict__ Wv) {
    const int which = blockIdx.y;
    const float* W = (which == 0) ? Wq : (which == 1) ? Wk : Wv;
    int idx = blockIdx.x * 256 + threadIdx.x;
    float4 wv = ((const float4*)W)[idx];
    int a4 = idx & 15;
    int d  = (idx >> 4) & 1023;
    int h  = idx >> 14;
    int nb = h * AA + a4 * 4;
    float vals[4] = {wv.x, wv.y, wv.z, wv.w};
    if (which == 2) {
        #pragma unroll
        for (int j = 0; j < 4; j++)
            g_wf[(size_t)(nb + j) * DD + d] = __float2half(vals[j]);
        return;
    }
    bf16* wh = g_whi + (size_t)which * (NN * DD);
    bf16* wl = g_wlo + (size_t)which * (NN * DD);
    #pragma unroll
    for (int j = 0; j < 4; j++) {
        bf16 hi = __float2bfloat16(vals[j]);
        bf16 lo = __float2bfloat16(vals[j] - __bfloat162float(hi));
        size_t o = (size_t)(nb + j) * DD + d;
        wh[o] = hi;
        wl[o] = lo;
    }
}

// ======================= Q/K projection GEMM (bf16 3-term split, R12 structure) ==========
#define KC 32
#define XPHB 80                                // hi row pitch, bytes
#define POFF_WH 10240
#define POFF_XL 20480
#define POFF_WL 28672
#define PSTG_B 36864
#define PROJ_SMEM (3*PSTG_B)                   // 110592

__global__ __launch_bounds__(256, 2) void proj_mma(const float* __restrict__ bq,
                                                   const float* __restrict__ bk) {
    const int which = blockIdx.z;              // 0=q, 1=k
    const float* bias = (which == 0) ? bq : bk;
    const bf16* Xh = g_xhi + (size_t)which * BSD;
    const bf16* Xl = g_xlo + (size_t)which * BSD;
    const bf16* Wh = g_whi + (size_t)which * (NN * DD);
    const bf16* Wl = g_wlo + (size_t)which * (NN * DD);
    extern __shared__ bf16 sm[];
    const int t = threadIdx.x, lane = t & 31, wid = t >> 5;
    const int wm = wid & 3, wn = wid >> 2;
    const int r0 = blockIdx.x * 128, n0 = blockIdx.y * 128;
    const uint32_t sbase = smem_u32(sm);

    float c[2][8][4];
    #pragma unroll
    for (int mt = 0; mt < 2; mt++)
        #pragma unroll
        for (int nt = 0; nt < 8; nt++)
            #pragma unroll
            for (int i = 0; i < 4; i++) c[mt][nt][i] = 0.0f;

#define PROJ_ISSUE(kc_) do {                                                       \
    int k0_ = (kc_) * KC;                                                          \
    uint32_t stg_ = sbase + ((kc_) % 3) * PSTG_B;                                  \
    _Pragma("unroll")                                                              \
    for (int i = 0; i < 8; i++) {                                                  \
        int rem = ((i & 1) << 8) + t; int row = rem >> 2, cq = rem & 3;            \
        const bf16* src;  uint32_t dst;                                            \
        uint32_t osw = SW64((uint32_t)(row * 64 + cq * 16));                       \
        if      ((i >> 1) == 0) { src = Xh + (size_t)(r0 + row) * DD + k0_ + cq * 8; \
                                  dst = stg_ + row * XPHB + cq * 16; }             \
        else if ((i >> 1) == 1) { src = Wh + (size_t)(n0 + row) * DD + k0_ + cq * 8; \
                                  dst = stg_ + POFF_WH + row * XPHB + cq * 16; }   \
        else if ((i >> 1) == 2) { src = Xl + (size_t)(r0 + row) * DD + k0_ + cq * 8; \
                                  dst = stg_ + POFF_XL + osw; }                    \
        else                    { src = Wl + (size_t)(n0 + row) * DD + k0_ + cq * 8; \
                                  dst = stg_ + POFF_WL + osw; }                    \
        CPA16(dst, src);                                                           \
    } } while (0)

    PROJ_ISSUE(0);
    CPA_COMMIT();
    PROJ_ISSUE(1);
    CPA_COMMIT();
    #pragma unroll 1
    for (int kc = 0; kc < DD / KC; kc++) {
        if (kc + 1 < DD / KC) CPA_WAIT(1); else CPA_WAIT(0);
        __syncthreads();
        if (kc + 2 < DD / KC) {
            PROJ_ISSUE(kc + 2);
            CPA_COMMIT();
        }

        const uint32_t stage = sbase + (kc % 3) * PSTG_B;
        #pragma unroll
        for (int ka = 0; ka < 2; ka++) {
            uint32_t xh[2][4], xl[2][4];
            #pragma unroll
            for (int mt = 0; mt < 2; mt++) {
                int arow = wm * 32 + mt * 16 + (lane & 15);
                int acolB = ka * 32 + (lane >> 4) * 16;
                ldsm4(xh[mt], stage + arow * XPHB + acolB);
                ldsm4(xl[mt], stage + POFF_XL + SW64((uint32_t)(arow * 64 + acolB)));
            }
            #pragma unroll
            for (int jp = 0; jp < 4; jp++) {
                uint32_t wh[4], wl[4];
                int brow = wn * 64 + jp * 16 + (lane & 7) + ((lane & 16) ? 8 : 0);
                int bcolB = ka * 32 + ((lane >> 3) & 1) * 16;
                ldsm4(wh, stage + POFF_WH + brow * XPHB + bcolB);
                ldsm4(wl, stage + POFF_WL + SW64((uint32_t)(brow * 64 + bcolB)));
                #pragma unroll
                for (int mt = 0; mt < 2; mt++) {
                    mma16816(c[mt][2*jp],   xh[mt], &wh[0]);
                    mma16816(c[mt][2*jp],   xh[mt], &wl[0]);
                    mma16816(c[mt][2*jp],   xl[mt], &wh[0]);
                    mma16816(c[mt][2*jp+1], xh[mt], &wh[2]);
                    mma16816(c[mt][2*jp+1], xh[mt], &wl[2]);
                    mma16816(c[mt][2*jp+1], xl[mt], &wh[2]);
                }
            }
        }
    }

    // epilogue: +bias, split to hi/lo bf16
    const int g = lane >> 2, l = lane & 3;
    bf16 *outhi = (which == 0) ? g_qhi : g_khi;
    bf16 *outlo = (which == 0) ? g_qlo : g_klo;
    #pragma unroll
    for (int mt = 0; mt < 2; mt++) {
        int row = r0 + wm * 32 + mt * 16 + g;
        int b = row >> 11, s = row & (SS - 1);
        #pragma unroll
        for (int nt = 0; nt < 8; nt++) {
            int n = n0 + wn * 64 + nt * 8 + l * 2;
            int h = n >> 6, a = n & 63;
            size_t off = ((size_t)(b * HH + h) * SS + s) * AA + a;
            float bv0 = bias[n], bv1 = bias[n + 1];
            uint32_t hi, lo;
            split2(c[mt][nt][0] + bv0, c[mt][nt][1] + bv1, hi, lo);
            *(uint32_t*)(outhi + off) = hi;
            *(uint32_t*)(outlo + off) = lo;
            split2(c[mt][nt][2] + bv0, c[mt][nt][3] + bv1, hi, lo);
            *(uint32_t*)(outhi + off + 8 * AA) = hi;
            *(uint32_t*)(outlo + off + 8 * AA) = lo;
        }
    }
}

// ======================= V projection GEMM (single fp16 term) =======================
// tile 128x128, 256 thr, warps 4(m)x2(n), KC=64, 3-stage ring, one barrier/chunk.
#define VKC 64
#define VSTG_B 32768                           // Xf(16K) + Wf(16K)
#define VOFF_W 16384
#define PROJV_SMEM (3*VSTG_B)                  // 98304

__global__ __launch_bounds__(256, 2) void proj_v(const float* __restrict__ bv) {
    extern __shared__ char smv[];
    const int t = threadIdx.x, lane = t & 31, wid = t >> 5;
    const int wm = wid & 3, wn = wid >> 2;
    const int r0 = blockIdx.x * 128, n0 = blockIdx.y * 128;
    const uint32_t sbase = smem_u32(smv);

    float c[2][8][4];
    #pragma unroll
    for (int mt = 0; mt < 2; mt++)
        #pragma unroll
        for (int nt = 0; nt < 8; nt++)
            #pragma unroll
            for (int i = 0; i < 4; i++) c[mt][nt][i] = 0.0f;

    // 8 cp.async 16B per thread per chunk: 2 tiles x 128 rows x 8 quads
#define PROJV_ISSUE(kc_) do {                                                      \
    int k0_ = (kc_) * VKC;                                                         \
    uint32_t stg_ = sbase + ((kc_) % 3) * VSTG_B;                                  \
    _Pragma("unroll")                                                              \
    for (int i = 0; i < 8; i++) {                                                  \
        int idx = i * 256 + t; int tile = idx >> 10;                               \
        int rem = idx & 1023; int row = rem >> 3, cq = rem & 7;                    \
        const __half* src = tile ? (g_wf + (size_t)(n0 + row) * DD + k0_ + cq * 8) \
                                 : (g_xf + (size_t)(r0 + row) * DD + k0_ + cq * 8);\
        uint32_t dst = stg_ + tile * VOFF_W + row * 128 + SWC(cq * 16, row);       \
        CPA16(dst, src);                                                           \
    } } while (0)

    PROJV_ISSUE(0);
    CPA_COMMIT();
    PROJV_ISSUE(1);
    CPA_COMMIT();
    #pragma unroll 1
    for (int kc = 0; kc < DD / VKC; kc++) {
        if (kc + 1 < DD / VKC) CPA_WAIT(1); else CPA_WAIT(0);
        __syncthreads();
        if (kc + 2 < DD / VKC) {
            PROJV_ISSUE(kc + 2);
            CPA_COMMIT();
        }

        const uint32_t stage = sbase + (kc % 3) * VSTG_B;
        #pragma unroll
        for (int ka = 0; ka < 4; ka++) {
            uint32_t xa[2][4];
            #pragma unroll
            for (int mt = 0; mt < 2; mt++) {
                int arow = wm * 32 + mt * 16 + (lane & 15);
                int acolB = ka * 32 + (lane >> 4) * 16;
                ldsm4(xa[mt], stage + arow * 128 + SWC(acolB, arow));
            }
            #pragma unroll
            for (int jp = 0; jp < 4; jp++) {
                uint32_t wb[4];
                int brow = wn * 64 + jp * 16 + (lane & 7) + ((lane & 16) ? 8 : 0);
                int bcolB = ka * 32 + ((lane >> 3) & 1) * 16;
                ldsm4(wb, stage + VOFF_W + brow * 128 + SWC(bcolB, brow));
                #pragma unroll
                for (int mt = 0; mt < 2; mt++) {
                    mma16816h(c[mt][2*jp],   xa[mt], &wb[0]);
                    mma16816h(c[mt][2*jp+1], xa[mt], &wb[2]);
                }
            }
        }
    }

    // epilogue: +bias, fp16 store
    const int g = lane >> 2, l = lane & 3;
    #pragma unroll
    for (int mt = 0; mt < 2; mt++) {
        int row = r0 + wm * 32 + mt * 16 + g;
        int b = row >> 11, s = row & (SS - 1);
        #pragma unroll
        for (int nt = 0; nt < 8; nt++) {
            int n = n0 + wn * 64 + nt * 8 + l * 2;
            int h = n >> 6, a = n & 63;
            size_t off = ((size_t)(b * HH + h) * SS + s) * AA + a;
            float bv0 = bv[n], bv1 = bv[n + 1];
            *(uint32_t*)(g_vh2 + off)          = packh2(c[mt][nt][0] + bv0, c[mt][nt][1] + bv1);
            *(uint32_t*)(g_vh2 + off + 8 * AA) = packh2(c[mt][nt][2] + bv0, c[mt][nt][3] + bv1);
        }
    }
}

// ======================= flash attention (identical to R12 best) =======================
#define AOFF_QL 16384
#define AOFF_ST 32768
#define ASTG3_B 24576
#define AOFF_KL 8192
#define AOFF_V  16384
#define ATTN_SMEM (AOFF_ST + 3*ASTG3_B)        // 106496 bytes
#define NT (SS/64)

__global__ __launch_bounds__(256, 2) void attn_mma(float* __restrict__ out) {
    extern __shared__ char smc[];

    const int bh = blockIdx.y, q0 = blockIdx.x * 128;
    const int t = threadIdx.x, lane = t & 31, wid = t >> 5;
    const int m0w = wid * 16;
    const size_t bhoff = (size_t)bh * SS * AA;
    const uint32_t sb = smem_u32(smc);

#define ATTN_ISSUE(kt_) do {                                                      \
    const size_t toff_ = bhoff + (size_t)(kt_) * 64 * AA;                         \
    uint32_t stg_ = sb + AOFF_ST + ((kt_) % 3) * ASTG3_B;                         \
    _Pragma("unroll")                                                             \
    for (int i = 0; i < 2; i++) {                                                 \
        int idx = t + i * 256; int row = idx >> 3, cq = idx & 7;                  \
        uint32_t so = stg_ + row * 128 + SWC(cq * 16, row);                       \
        size_t go = toff_ + row * AA + cq * 8;                                    \
        CPA16(so,             g_khi + go);                                        \
        CPA16(so + AOFF_KL,   g_klo + go);                                        \
        CPA16(so + AOFF_V,    g_vh2 + go);                                        \
    } } while (0)

    {
        const bf16* Qghi = g_qhi + bhoff + (size_t)q0 * AA;
        const bf16* Qglo = g_qlo + bhoff + (size_t)q0 * AA;
        #pragma unroll
        for (int i = 0; i < 4; i++) {
            int idx = t + i * 256;
            int row = idx >> 3, cq = idx & 7;
            uint32_t off = row * 128 + SWC(cq * 16, row);
            *(uint4*)(smc + off)           = *(const uint4*)(Qghi + row * AA + cq * 8);
            *(uint4*)(smc + AOFF_QL + off) = *(const uint4*)(Qglo + row * AA + cq * 8);
        }
    }

    ATTN_ISSUE(0);
    CPA_COMMIT();
    ATTN_ISSUE(1);
    CPA_COMMIT();

    float o[8][4];
    float ls[4] = {0.0f, 0.0f, 0.0f, 0.0f};
    #pragma unroll
    for (int j = 0; j < 8; j++)
        #pragma unroll
        for (int i = 0; i < 4; i++) o[j][i] = 0.0f;
    float mi0 = -INFINITY, mi1 = -INFINITY;
    const uint32_t onesb[2] = {ONESH2, ONESH2};

    #pragma unroll 1
    for (int kt = 0; kt < NT; kt++) {
        if (kt + 1 < NT) CPA_WAIT(1); else CPA_WAIT(0);
        __syncthreads();
        if (kt + 2 < NT) {
            ATTN_ISSUE(kt + 2);
            CPA_COMMIT();
        }
        const uint32_t stg = sb + AOFF_ST + (kt % 3) * ASTG3_B;

        float s[8][4];
        #pragma unroll
        for (int j = 0; j < 8; j++)
            #pragma unroll
            for (int i = 0; i < 4; i++) s[j][i] = 0.0f;

        #pragma unroll
        for (int ka = 0; ka < 4; ka++) {
            uint32_t qh[4], ql[4];
            int qrow = m0w + (lane & 15);
            int qcolB = ka * 32 + (lane >> 4) * 16;
            uint32_t qaddr = sb + qrow * 128 + SWC(qcolB, qrow);
            ldsm4(qh, qaddr);
            ldsm4(ql, qaddr + AOFF_QL);
            #pragma unroll
            for (int jp = 0; jp < 4; jp++) {
                uint32_t kh4[4], kl4[4];
                int krow = jp * 16 + (lane & 7) + ((lane & 16) ? 8 : 0);
                int kcolB = ka * 32 + ((lane >> 3) & 1) * 16;
                uint32_t kaddr = stg + krow * 128 + SWC(kcolB, krow);
                ldsm4(kh4, kaddr);
                ldsm4(kl4, kaddr + AOFF_KL);
                mma16816(s[2*jp],   qh, &kh4[0]);
                mma16816(s[2*jp],   qh, &kl4[0]);
                mma16816(s[2*jp],   ql, &kh4[0]);
                mma16816(s[2*jp+1], qh, &kh4[2]);
                mma16816(s[2*jp+1], qh, &kl4[2]);
                mma16816(s[2*jp+1], ql, &kh4[2]);
            }
        }

        float tm0 = -INFINITY, tm1 = -INFINITY;
        #pragma unroll
        for (int j = 0; j < 8; j++) {
            tm0 = fmaxf(tm0, fmaxf(s[j][0], s[j][1]));
            tm1 = fmaxf(tm1, fmaxf(s[j][2], s[j][3]));
        }
        tm0 = fmaxf(tm0, __shfl_xor_sync(0xffffffffu, tm0, 1));
        tm0 = fmaxf(tm0, __shfl_xor_sync(0xffffffffu, tm0, 2));
        tm1 = fmaxf(tm1, __shfl_xor_sync(0xffffffffu, tm1, 1));
        tm1 = fmaxf(tm1, __shfl_xor_sync(0xffffffffu, tm1, 2));
        float mn0 = fmaxf(mi0, tm0), mn1 = fmaxf(mi1, tm1);
        if (tm0 > mi0 || tm1 > mi1) {
            float corr0 = ex2f((mi0 - mn0) * L2E);
            float corr1 = ex2f((mi1 - mn1) * L2E);
            #pragma unroll
            for (int j = 0; j < 8; j++) {
                o[j][0] *= corr0; o[j][1] *= corr0;
                o[j][2] *= corr1; o[j][3] *= corr1;
            }
            ls[0] *= corr0; ls[1] *= corr0; ls[2] *= corr1; ls[3] *= corr1;
            mi0 = mn0; mi1 = mn1;
        }
        const float b0 = -mi0 * L2E, b1 = -mi1 * L2E;
        uint32_t ps[8][2];
        #pragma unroll
        for (int j = 0; j < 8; j++) {
            ps[j][0] = ex2h2(packh2(fmaf(s[j][0], L2E, b0), fmaf(s[j][1], L2E, b0)));
            ps[j][1] = ex2h2(packh2(fmaf(s[j][2], L2E, b1), fmaf(s[j][3], L2E, b1)));
        }

        #pragma unroll
        for (int kc = 0; kc < 4; kc++) {
            uint32_t pa[4];
            pa[0] = ps[2*kc][0];
            pa[1] = ps[2*kc][1];
            pa[2] = ps[2*kc+1][0];
            pa[3] = ps[2*kc+1][1];
            mma16816h(ls, pa, onesb);
            #pragma unroll
            for (int jp = 0; jp < 4; jp++) {
                uint32_t vh4[4];
                int vrow = kc * 16 + (lane & 7) + ((lane >> 3) & 1) * 8;
                int vcolB = jp * 32 + ((lane & 16) ? 16 : 0);
                uint32_t vaddr = stg + AOFF_V + vrow * 128 + SWC(vcolB, vrow);
                ldsm4t(vh4, vaddr);
                mma16816h(o[2*jp],   pa, &vh4[0]);
                mma16816h(o[2*jp+1], pa, &vh4[2]);
            }
        }
    }

    const float inv0 = 1.0f / ls[0], inv1 = 1.0f / ls[2];
    const int g = lane >> 2, l = lane & 3;
    const int b = bh >> 4, h = bh & 15;
    const int row0 = q0 + m0w + g;
    float* outp = out + ((size_t)b * SS + row0) * NN + h * AA;
    #pragma unroll
    for (int j = 0; j < 8; j++) {
        float2 w0 = make_float2(o[j][0] * inv0, o[j][1] * inv0);
        float2 w1 = make_float2(o[j][2] * inv1, o[j][3] * inv1);
        *(float2*)(outp + j * 8 + l * 2) = w0;
        *(float2*)(outp + (size_t)8 * NN + j * 8 + l * 2) = w1;
    }
}

extern "C" void kernel_launch(void* const* d_in, const int* in_sizes, int n_in,
                              void* d_out, int out_size) {
    (void)in_sizes; (void)n_in; (void)out_size;
    const float* q  = (const float*)d_in[0];
    const float* k  = (const float*)d_in[1];
    const float* v  = (const float*)d_in[2];
    const float* Wq = (const float*)d_in[3];
    const float* bq = (const float*)d_in[4];
    const float* Wk = (const float*)d_in[5];
    const float* bk = (const float*)d_in[6];
    const float* Wv = (const float*)d_in[7];
    const float* bv = (const float*)d_in[8];
    float* out = (float*)d_out;

    cudaFuncSetAttribute(proj_mma, cudaFuncAttributeMaxDynamicSharedMemorySize, PROJ_SMEM);
    cudaFuncSetAttribute(proj_v, cudaFuncAttributeMaxDynamicSharedMemorySize, PROJV_SMEM);
    cudaFuncSetAttribute(attn_mma, cudaFuncAttributeMaxDynamicSharedMemorySize, ATTN_SMEM);

    cvt_x3<<<dim3(4096, 3), 256>>>(q, k, v);
    cvt_w3<<<dim3(1024, 3), 256>>>(Wq, Wk, Wv);
    proj_mma<<<dim3(64, 8, 2), 256, PROJ_SMEM>>>(bq, bk);
    proj_v<<<dim3(64, 8), 256, PROJV_SMEM>>>(bv);

    dim3 ag(SS / 128, BB * HH);
    attn_mma<<<ag, 256, ATTN_SMEM>>>(out);
}

// round 15
// speedup vs baseline: 1.2515x; 1.0184x over previous
#include <cuda_runtime.h>
#include <cuda_bf16.h>
#include <cuda_fp16.h>
#include <math.h>
#include <stdint.h>

#define BB 4
#define SS 2048
#define DD 1024
#define HH 16
#define AA 64
#define NN (HH*AA)   // 1024
#define BSD (BB*SS*DD)

typedef __nv_bfloat16 bf16;
typedef __nv_bfloat162 bf162;

// ---- scratch ----
__device__ bf16 g_qhi[BB*HH*SS*AA];
__device__ bf16 g_qlo[BB*HH*SS*AA];
__device__ bf16 g_khi[BB*HH*SS*AA];
__device__ bf16 g_klo[BB*HH*SS*AA];
__device__ __half g_vh2[BB*HH*SS*AA];        // V single fp16
__device__ bf16 g_xhi[2*BSD];                // q,k inputs split
__device__ bf16 g_xlo[2*BSD];
__device__ bf16 g_whi[2*NN*DD];
__device__ bf16 g_wlo[2*NN*DD];
__device__ __half g_xf[BSD];                 // v input fp16
__device__ __half g_wf[NN*DD];               // v weight fp16

// ======================= helpers =======================
__device__ __forceinline__ uint32_t smem_u32(const void* p) {
    uint32_t a;
    asm("{ .reg .u64 t; cvta.to.shared.u64 t, %1; cvt.u32.u64 %0, t; }" : "=r"(a) : "l"(p));
    return a;
}
__device__ __forceinline__ void mma16816(float* c, const uint32_t* a, const uint32_t* b) {
    asm volatile(
        "mma.sync.aligned.m16n8k16.row.col.f32.bf16.bf16.f32 "
        "{%0,%1,%2,%3}, {%4,%5,%6,%7}, {%8,%9}, {%0,%1,%2,%3};"
        : "+f"(c[0]), "+f"(c[1]), "+f"(c[2]), "+f"(c[3])
        : "r"(a[0]), "r"(a[1]), "r"(a[2]), "r"(a[3]), "r"(b[0]), "r"(b[1]));
}
__device__ __forceinline__ void mma16816h(float* c, const uint32_t* a, const uint32_t* b) {
    asm volatile(
        "mma.sync.aligned.m16n8k16.row.col.f32.f16.f16.f32 "
        "{%0,%1,%2,%3}, {%4,%5,%6,%7}, {%8,%9}, {%0,%1,%2,%3};"
        : "+f"(c[0]), "+f"(c[1]), "+f"(c[2]), "+f"(c[3])
        : "r"(a[0]), "r"(a[1]), "r"(a[2]), "r"(a[3]), "r"(b[0]), "r"(b[1]));
}
__device__ __forceinline__ void ldsm4(uint32_t* r, uint32_t addr) {
    asm volatile("ldmatrix.sync.aligned.m8n8.x4.shared.b16 {%0,%1,%2,%3}, [%4];"
        : "=r"(r[0]), "=r"(r[1]), "=r"(r[2]), "=r"(r[3]) : "r"(addr));
}
__device__ __forceinline__ void ldsm4t(uint32_t* r, uint32_t addr) {
    asm volatile("ldmatrix.sync.aligned.m8n8.x4.trans.shared.b16 {%0,%1,%2,%3}, [%4];"
        : "=r"(r[0]), "=r"(r[1]), "=r"(r[2]), "=r"(r[3]) : "r"(addr));
}
#define CPA16(dst_u32, src_ptr) \
    asm volatile("cp.async.cg.shared.global [%0], [%1], 16;" :: "r"(dst_u32), "l"(src_ptr))
#define CPA_COMMIT() asm volatile("cp.async.commit_group;" ::: "memory")
#define CPA_WAIT(n)  asm volatile("cp.async.wait_group %0;" :: "n"(n) : "memory")

__device__ __forceinline__ float ex2f(float x) {
    float r;
    asm("ex2.approx.f32 %0, %1;" : "=f"(r) : "f"(x));
    return r;
}
__device__ __forceinline__ uint32_t ex2h2(uint32_t a) {
    uint32_t r;
    asm("ex2.approx.f16x2 %0, %1;" : "=r"(r) : "r"(a));
    return r;
}
__device__ __forceinline__ uint32_t packh2(float a, float b) {
    __half2 h = __floats2half2_rn(a, b);      // x = a (low), y = b (high)
    return *reinterpret_cast<uint32_t*>(&h);
}
__device__ __forceinline__ uint32_t packbf2(float a, float b) {
    bf162 h = __floats2bfloat162_rn(a, b);
    return *reinterpret_cast<uint32_t*>(&h);
}
__device__ __forceinline__ void split2(float p0, float p1, uint32_t& hi, uint32_t& lo) {
    bf162 h = __floats2bfloat162_rn(p0, p1);
    bf162 l = __floats2bfloat162_rn(p0 - __bfloat162float(h.x), p1 - __bfloat162float(h.y));
    hi = *reinterpret_cast<uint32_t*>(&h);
    lo = *reinterpret_cast<uint32_t*>(&l);
}
#define L2E 1.4426950408889634f
#define ONESH2 0x3C003C00u                    // fp16 (1.0, 1.0)
#define SW64(o) ((o) ^ (((o) >> 3) & 0x30))   // conflict-free swizzle for 64B rows
#define SWC(colB, row) ((uint32_t)((colB) ^ (((row) & 7) << 4)))  // 128B-row swizzle

// ======================= fused conversion kernel =======================
// grid (5120, 3): x < 4096 -> input tensor path (8 floats/thread); else weight path.
__global__ __launch_bounds__(256) void cvt_all(const float* __restrict__ q,
                                               const float* __restrict__ k,
                                               const float* __restrict__ v,
                                               const float* __restrict__ Wq,
                                               const float* __restrict__ Wk,
                                               const float* __restrict__ Wv) {
    const int which = blockIdx.y;
    if (blockIdx.x < 4096) {
        const float* X = (which == 0) ? q : (which == 1) ? k : v;
        int i = blockIdx.x * 256 + threadIdx.x;    // 0..BSD/8-1
        float4 a = ((const float4*)X)[2*i];
        float4 b = ((const float4*)X)[2*i+1];
        float f[8] = {a.x, a.y, a.z, a.w, b.x, b.y, b.z, b.w};
        if (which == 2) {
            uint32_t hw[4];
            #pragma unroll
            for (int j = 0; j < 4; j++) hw[j] = packh2(f[2*j], f[2*j+1]);
            ((uint4*)g_xf)[i] = make_uint4(hw[0], hw[1], hw[2], hw[3]);
            return;
        }
        bf16* xh = g_xhi + (size_t)which * BSD;
        bf16* xl = g_xlo + (size_t)which * BSD;
        uint32_t hw[4], lw[4];
        #pragma unroll
        for (int j = 0; j < 4; j++) {
            bf16 h0 = __float2bfloat16(f[2*j]);
            bf16 h1 = __float2bfloat16(f[2*j+1]);
            float l0 = f[2*j]   - __bfloat162float(h0);
            float l1 = f[2*j+1] - __bfloat162float(h1);
            bf162 hh = __halves2bfloat162(h0, h1);
            hw[j] = *reinterpret_cast<uint32_t*>(&hh);
            lw[j] = packbf2(l0, l1);
        }
        ((uint4*)xh)[i] = make_uint4(hw[0], hw[1], hw[2], hw[3]);
        ((uint4*)xl)[i] = make_uint4(lw[0], lw[1], lw[2], lw[3]);
    } else {
        const float* W = (which == 0) ? Wq : (which == 1) ? Wk : Wv;
        int idx = (blockIdx.x - 4096) * 256 + threadIdx.x;   // float4 over [H,D,A]
        float4 wv = ((const float4*)W)[idx];
        int a4 = idx & 15;
        int d  = (idx >> 4) & 1023;
        int h  = idx >> 14;
        int nb = h * AA + a4 * 4;
        float vals[4] = {wv.x, wv.y, wv.z, wv.w};
        if (which == 2) {
            #pragma unroll
            for (int j = 0; j < 4; j++)
                g_wf[(size_t)(nb + j) * DD + d] = __float2half(vals[j]);
            return;
        }
        bf16* wh = g_whi + (size_t)which * (NN * DD);
        bf16* wl = g_wlo + (size_t)which * (NN * DD);
        #pragma unroll
        for (int j = 0; j < 4; j++) {
            bf16 hi = __float2bfloat16(vals[j]);
            bf16 lo = __float2bfloat16(vals[j] - __bfloat162float(hi));
            size_t o = (size_t)(nb + j) * DD + d;
            wh[o] = hi;
            wl[o] = lo;
        }
    }
}

// ======================= fused projection GEMM =======================
// grid (64, 8, 3): z<2 = bf16-split q/k path; z=2 = single-fp16 V path.
// Both: tile 128x128, 256 thr, warps 4(m)x2(n), 3-stage single-barrier cp.async ring.
#define KC 32
#define XPHB 80
#define POFF_WH 10240
#define POFF_XL 20480
#define POFF_WL 28672
#define PSTG_B 36864
#define PROJ_SMEM (3*PSTG_B)                   // 110592
#define VKC 64
#define VSTG_B 32768
#define VOFF_W 16384

__global__ __launch_bounds__(256, 2) void proj_all(const float* __restrict__ bq,
                                                   const float* __restrict__ bk,
                                                   const float* __restrict__ bv) {
    extern __shared__ char smp[];
    const int which = blockIdx.z;
    const int t = threadIdx.x, lane = t & 31, wid = t >> 5;
    const int wm = wid & 3, wn = wid >> 2;
    const int r0 = blockIdx.x * 128, n0 = blockIdx.y * 128;
    const uint32_t sbase = smem_u32(smp);
    const int g = lane >> 2, l = lane & 3;

    float c[2][8][4];
    #pragma unroll
    for (int mt = 0; mt < 2; mt++)
        #pragma unroll
        for (int nt = 0; nt < 8; nt++)
            #pragma unroll
            for (int i = 0; i < 4; i++) c[mt][nt][i] = 0.0f;

    if (which < 2) {
        // ---------- bf16 3-term split path (q, k) ----------
        const float* bias = (which == 0) ? bq : bk;
        const bf16* Xh = g_xhi + (size_t)which * BSD;
        const bf16* Xl = g_xlo + (size_t)which * BSD;
        const bf16* Wh = g_whi + (size_t)which * (NN * DD);
        const bf16* Wl = g_wlo + (size_t)which * (NN * DD);

#define PROJ_ISSUE(kc_) do {                                                       \
    int k0_ = (kc_) * KC;                                                          \
    uint32_t stg_ = sbase + ((kc_) % 3) * PSTG_B;                                  \
    _Pragma("unroll")                                                              \
    for (int i = 0; i < 8; i++) {                                                  \
        int rem = ((i & 1) << 8) + t; int row = rem >> 2, cq = rem & 3;            \
        const bf16* src;  uint32_t dst;                                            \
        uint32_t osw = SW64((uint32_t)(row * 64 + cq * 16));                       \
        if      ((i >> 1) == 0) { src = Xh + (size_t)(r0 + row) * DD + k0_ + cq * 8; \
                                  dst = stg_ + row * XPHB + cq * 16; }             \
        else if ((i >> 1) == 1) { src = Wh + (size_t)(n0 + row) * DD + k0_ + cq * 8; \
                                  dst = stg_ + POFF_WH + row * XPHB + cq * 16; }   \
        else if ((i >> 1) == 2) { src = Xl + (size_t)(r0 + row) * DD + k0_ + cq * 8; \
                                  dst = stg_ + POFF_XL + osw; }                    \
        else                    { src = Wl + (size_t)(n0 + row) * DD + k0_ + cq * 8; \
                                  dst = stg_ + POFF_WL + osw; }                    \
        CPA16(dst, src);                                                           \
    } } while (0)

        PROJ_ISSUE(0);
        CPA_COMMIT();
        PROJ_ISSUE(1);
        CPA_COMMIT();
        #pragma unroll 1
        for (int kc = 0; kc < DD / KC; kc++) {
            if (kc + 1 < DD / KC) CPA_WAIT(1); else CPA_WAIT(0);
            __syncthreads();
            if (kc + 2 < DD / KC) {
                PROJ_ISSUE(kc + 2);
                CPA_COMMIT();
            }

            const uint32_t stage = sbase + (kc % 3) * PSTG_B;
            #pragma unroll
            for (int ka = 0; ka < 2; ka++) {
                uint32_t xh[2][4], xl[2][4];
                #pragma unroll
                for (int mt = 0; mt < 2; mt++) {
                    int arow = wm * 32 + mt * 16 + (lane & 15);
                    int acolB = ka * 32 + (lane >> 4) * 16;
                    ldsm4(xh[mt], stage + arow * XPHB + acolB);
                    ldsm4(xl[mt], stage + POFF_XL + SW64((uint32_t)(arow * 64 + acolB)));
                }
                #pragma unroll
                for (int jp = 0; jp < 4; jp++) {
                    uint32_t wh[4], wl[4];
                    int brow = wn * 64 + jp * 16 + (lane & 7) + ((lane & 16) ? 8 : 0);
                    int bcolB = ka * 32 + ((lane >> 3) & 1) * 16;
                    ldsm4(wh, stage + POFF_WH + brow * XPHB + bcolB);
                    ldsm4(wl, stage + POFF_WL + SW64((uint32_t)(brow * 64 + bcolB)));
                    #pragma unroll
                    for (int mt = 0; mt < 2; mt++) {
                        mma16816(c[mt][2*jp],   xh[mt], &wh[0]);
                        mma16816(c[mt][2*jp],   xh[mt], &wl[0]);
                        mma16816(c[mt][2*jp],   xl[mt], &wh[0]);
                        mma16816(c[mt][2*jp+1], xh[mt], &wh[2]);
                        mma16816(c[mt][2*jp+1], xh[mt], &wl[2]);
                        mma16816(c[mt][2*jp+1], xl[mt], &wh[2]);
                    }
                }
            }
        }

        bf16 *outhi = (which == 0) ? g_qhi : g_khi;
        bf16 *outlo = (which == 0) ? g_qlo : g_klo;
        #pragma unroll
        for (int mt = 0; mt < 2; mt++) {
            int row = r0 + wm * 32 + mt * 16 + g;
            int b = row >> 11, s = row & (SS - 1);
            #pragma unroll
            for (int nt = 0; nt < 8; nt++) {
                int n = n0 + wn * 64 + nt * 8 + l * 2;
                int h = n >> 6, a = n & 63;
                size_t off = ((size_t)(b * HH + h) * SS + s) * AA + a;
                float bv0 = bias[n], bv1 = bias[n + 1];
                uint32_t hi, lo;
                split2(c[mt][nt][0] + bv0, c[mt][nt][1] + bv1, hi, lo);
                *(uint32_t*)(outhi + off) = hi;
                *(uint32_t*)(outlo + off) = lo;
                split2(c[mt][nt][2] + bv0, c[mt][nt][3] + bv1, hi, lo);
                *(uint32_t*)(outhi + off + 8 * AA) = hi;
                *(uint32_t*)(outlo + off + 8 * AA) = lo;
            }
        }
    } else {
        // ---------- single-fp16 path (V) ----------
#define PROJV_ISSUE(kc_) do {                                                      \
    int k0_ = (kc_) * VKC;                                                         \
    uint32_t stg_ = sbase + ((kc_) % 3) * VSTG_B;                                  \
    _Pragma("unroll")                                                              \
    for (int i = 0; i < 8; i++) {                                                  \
        int idx = i * 256 + t; int tile = idx >> 10;                               \
        int rem = idx & 1023; int row = rem >> 3, cq = rem & 7;                    \
        const __half* src = tile ? (g_wf + (size_t)(n0 + row) * DD + k0_ + cq * 8) \
                                 : (g_xf + (size_t)(r0 + row) * DD + k0_ + cq * 8);\
        uint32_t dst = stg_ + tile * VOFF_W + row * 128 + SWC(cq * 16, row);       \
        CPA16(dst, src);                                                           \
    } } while (0)

        PROJV_ISSUE(0);
        CPA_COMMIT();
        PROJV_ISSUE(1);
        CPA_COMMIT();
        #pragma unroll 1
        for (int kc = 0; kc < DD / VKC; kc++) {
            if (kc + 1 < DD / VKC) CPA_WAIT(1); else CPA_WAIT(0);
            __syncthreads();
            if (kc + 2 < DD / VKC) {
                PROJV_ISSUE(kc + 2);
                CPA_COMMIT();
            }

            const uint32_t stage = sbase + (kc % 3) * VSTG_B;
            #pragma unroll
            for (int ka = 0; ka < 4; ka++) {
                uint32_t xa[2][4];
                #pragma unroll
                for (int mt = 0; mt < 2; mt++) {
                    int arow = wm * 32 + mt * 16 + (lane & 15);
                    int acolB = ka * 32 + (lane >> 4) * 16;
                    ldsm4(xa[mt], stage + arow * 128 + SWC(acolB, arow));
                }
                #pragma unroll
                for (int jp = 0; jp < 4; jp++) {
                    uint32_t wb[4];
                    int brow = wn * 64 + jp * 16 + (lane & 7) + ((lane & 16) ? 8 : 0);
                    int bcolB = ka * 32 + ((lane >> 3) & 1) * 16;
                    ldsm4(wb, stage + VOFF_W + brow * 128 + SWC(bcolB, brow));
                    #pragma unroll
                    for (int mt = 0; mt < 2; mt++) {
                        mma16816h(c[mt][2*jp],   xa[mt], &wb[0]);
                        mma16816h(c[mt][2*jp+1], xa[mt], &wb[2]);
                    }
                }
            }
        }

        #pragma unroll
        for (int mt = 0; mt < 2; mt++) {
            int row = r0 + wm * 32 + mt * 16 + g;
            int b = row >> 11, s = row & (SS - 1);
            #pragma unroll
            for (int nt = 0; nt < 8; nt++) {
                int n = n0 + wn * 64 + nt * 8 + l * 2;
                int h = n >> 6, a = n & 63;
                size_t off = ((size_t)(b * HH + h) * SS + s) * AA + a;
                float bv0 = bv[n], bv1 = bv[n + 1];
                *(uint32_t*)(g_vh2 + off)          = packh2(c[mt][nt][0] + bv0, c[mt][nt][1] + bv1);
                *(uint32_t*)(g_vh2 + off + 8 * AA) = packh2(c[mt][nt][2] + bv0, c[mt][nt][3] + bv1);
            }
        }
    }
}

// ======================= flash attention (identical to R13 best) =======================
#define AOFF_QL 16384
#define AOFF_ST 32768
#define ASTG3_B 24576
#define AOFF_KL 8192
#define AOFF_V  16384
#define ATTN_SMEM (AOFF_ST + 3*ASTG3_B)        // 106496 bytes
#define NT (SS/64)

__global__ __launch_bounds__(256, 2) void attn_mma(float* __restrict__ out) {
    extern __shared__ char smc[];

    const int bh = blockIdx.y, q0 = blockIdx.x * 128;
    const int t = threadIdx.x, lane = t & 31, wid = t >> 5;
    const int m0w = wid * 16;
    const size_t bhoff = (size_t)bh * SS * AA;
    const uint32_t sb = smem_u32(smc);

#define ATTN_ISSUE(kt_) do {                                                      \
    const size_t toff_ = bhoff + (size_t)(kt_) * 64 * AA;                         \
    uint32_t stg_ = sb + AOFF_ST + ((kt_) % 3) * ASTG3_B;                         \
    _Pragma("unroll")                                                             \
    for (int i = 0; i < 2; i++) {                                                 \
        int idx = t + i * 256; int row = idx >> 3, cq = idx & 7;                  \
        uint32_t so = stg_ + row * 128 + SWC(cq * 16, row);                       \
        size_t go = toff_ + row * AA + cq * 8;                                    \
        CPA16(so,             g_khi + go);                                        \
        CPA16(so + AOFF_KL,   g_klo + go);                                        \
        CPA16(so + AOFF_V,    g_vh2 + go);                                        \
    } } while (0)

    {
        const bf16* Qghi = g_qhi + bhoff + (size_t)q0 * AA;
        const bf16* Qglo = g_qlo + bhoff + (size_t)q0 * AA;
        #pragma unroll
        for (int i = 0; i < 4; i++) {
            int idx = t + i * 256;
            int row = idx >> 3, cq = idx & 7;
            uint32_t off = row * 128 + SWC(cq * 16, row);
            *(uint4*)(smc + off)           = *(const uint4*)(Qghi + row * AA + cq * 8);
            *(uint4*)(smc + AOFF_QL + off) = *(const uint4*)(Qglo + row * AA + cq * 8);
        }
    }

    ATTN_ISSUE(0);
    CPA_COMMIT();
    ATTN_ISSUE(1);
    CPA_COMMIT();

    float o[8][4];
    float ls[4] = {0.0f, 0.0f, 0.0f, 0.0f};
    #pragma unroll
    for (int j = 0; j < 8; j++)
        #pragma unroll
        for (int i = 0; i < 4; i++) o[j][i] = 0.0f;
    float mi0 = -INFINITY, mi1 = -INFINITY;
    const uint32_t onesb[2] = {ONESH2, ONESH2};

    #pragma unroll 1
    for (int kt = 0; kt < NT; kt++) {
        if (kt + 1 < NT) CPA_WAIT(1); else CPA_WAIT(0);
        __syncthreads();
        if (kt + 2 < NT) {
            ATTN_ISSUE(kt + 2);
            CPA_COMMIT();
        }
        const uint32_t stg = sb + AOFF_ST + (kt % 3) * ASTG3_B;

        float s[8][4];
        #pragma unroll
        for (int j = 0; j < 8; j++)
            #pragma unroll
            for (int i = 0; i < 4; i++) s[j][i] = 0.0f;

        #pragma unroll
        for (int ka = 0; ka < 4; ka++) {
            uint32_t qh[4], ql[4];
            int qrow = m0w + (lane & 15);
            int qcolB = ka * 32 + (lane >> 4) * 16;
            uint32_t qaddr = sb + qrow * 128 + SWC(qcolB, qrow);
            ldsm4(qh, qaddr);
            ldsm4(ql, qaddr + AOFF_QL);
            #pragma unroll
            for (int jp = 0; jp < 4; jp++) {
                uint32_t kh4[4], kl4[4];
                int krow = jp * 16 + (lane & 7) + ((lane & 16) ? 8 : 0);
                int kcolB = ka * 32 + ((lane >> 3) & 1) * 16;
                uint32_t kaddr = stg + krow * 128 + SWC(kcolB, krow);
                ldsm4(kh4, kaddr);
                ldsm4(kl4, kaddr + AOFF_KL);
                mma16816(s[2*jp],   qh, &kh4[0]);
                mma16816(s[2*jp],   qh, &kl4[0]);
                mma16816(s[2*jp],   ql, &kh4[0]);
                mma16816(s[2*jp+1], qh, &kh4[2]);
                mma16816(s[2*jp+1], qh, &kl4[2]);
                mma16816(s[2*jp+1], ql, &kh4[2]);
            }
        }

        float tm0 = -INFINITY, tm1 = -INFINITY;
        #pragma unroll
        for (int j = 0; j < 8; j++) {
            tm0 = fmaxf(tm0, fmaxf(s[j][0], s[j][1]));
            tm1 = fmaxf(tm1, fmaxf(s[j][2], s[j][3]));
        }
        tm0 = fmaxf(tm0, __shfl_xor_sync(0xffffffffu, tm0, 1));
        tm0 = fmaxf(tm0, __shfl_xor_sync(0xffffffffu, tm0, 2));
        tm1 = fmaxf(tm1, __shfl_xor_sync(0xffffffffu, tm1, 1));
        tm1 = fmaxf(tm1, __shfl_xor_sync(0xffffffffu, tm1, 2));
        float mn0 = fmaxf(mi0, tm0), mn1 = fmaxf(mi1, tm1);
        if (tm0 > mi0 || tm1 > mi1) {
            float corr0 = ex2f((mi0 - mn0) * L2E);
            float corr1 = ex2f((mi1 - mn1) * L2E);
            #pragma unroll
            for (int j = 0; j < 8; j++) {
                o[j][0] *= corr0; o[j][1] *= corr0;
                o[j][2] *= corr1; o[j][3] *= corr1;
            }
            ls[0] *= corr0; ls[1] *= corr0; ls[2] *= corr1; ls[3] *= corr1;
            mi0 = mn0; mi1 = mn1;
        }
        const float b0 = -mi0 * L2E, b1 = -mi1 * L2E;
        uint32_t ps[8][2];
        #pragma unroll
        for (int j = 0; j < 8; j++) {
            ps[j][0] = ex2h2(packh2(fmaf(s[j][0], L2E, b0), fmaf(s[j][1], L2E, b0)));
            ps[j][1] = ex2h2(packh2(fmaf(s[j][2], L2E, b1), fmaf(s[j][3], L2E, b1)));
        }

        #pragma unroll
        for (int kc = 0; kc < 4; kc++) {
            uint32_t pa[4];
            pa[0] = ps[2*kc][0];
            pa[1] = ps[2*kc][1];
            pa[2] = ps[2*kc+1][0];
            pa[3] = ps[2*kc+1][1];
            mma16816h(ls, pa, onesb);
            #pragma unroll
            for (int jp = 0; jp < 4; jp++) {
                uint32_t vh4[4];
                int vrow = kc * 16 + (lane & 7) + ((lane >> 3) & 1) * 8;
                int vcolB = jp * 32 + ((lane & 16) ? 16 : 0);
                uint32_t vaddr = stg + AOFF_V + vrow * 128 + SWC(vcolB, vrow);
                ldsm4t(vh4, vaddr);
                mma16816h(o[2*jp],   pa, &vh4[0]);
                mma16816h(o[2*jp+1], pa, &vh4[2]);
            }
        }
    }

    const float inv0 = 1.0f / ls[0], inv1 = 1.0f / ls[2];
    const int g = lane >> 2, l = lane & 3;
    const int b = bh >> 4, h = bh & 15;
    const int row0 = q0 + m0w + g;
    float* outp = out + ((size_t)b * SS + row0) * NN + h * AA;
    #pragma unroll
    for (int j = 0; j < 8; j++) {
        float2 w0 = make_float2(o[j][0] * inv0, o[j][1] * inv0);
        float2 w1 = make_float2(o[j][2] * inv1, o[j][3] * inv1);
        *(float2*)(outp + j * 8 + l * 2) = w0;
        *(float2*)(outp + (size_t)8 * NN + j * 8 + l * 2) = w1;
    }
}

extern "C" void kernel_launch(void* const* d_in, const int* in_sizes, int n_in,
                              void* d_out, int out_size) {
    (void)in_sizes; (void)n_in; (void)out_size;
    const float* q  = (const float*)d_in[0];
    const float* k  = (const float*)d_in[1];
    const float* v  = (const float*)d_in[2];
    const float* Wq = (const float*)d_in[3];
    const float* bq = (const float*)d_in[4];
    const float* Wk = (const float*)d_in[5];
    const float* bk = (const float*)d_in[6];
    const float* Wv = (const float*)d_in[7];
    const float* bv = (const float*)d_in[8];
    float* out = (float*)d_out;

    cudaFuncSetAttribute(proj_all, cudaFuncAttributeMaxDynamicSharedMemorySize, PROJ_SMEM);
    cudaFuncSetAttribute(attn_mma, cudaFuncAttributeMaxDynamicSharedMemorySize, ATTN_SMEM);

    cvt_all<<<dim3(5120, 3), 256>>>(q, k, v, Wq, Wk, Wv);
    proj_all<<<dim3(64, 8, 3), 256, PROJ_SMEM>>>(bq, bk, bv);

    dim3 ag(SS / 128, BB * HH);
    attn_mma<<<ag, 256, ATTN_SMEM>>>(out);
}